// round 13
// baseline (speedup 1.0000x reference)
#include <cuda_runtime.h>
#include <cuda_bf16.h>
#include <cstdint>
#include <math.h>

#define TT 1500
#define BB 16
#define DD 512
#define HH 1024
#define KEEPF 0.8f
#define EPSF 1e-5f
#define NTOT (TT*BB*HH)
#define GRID_SCAN 128
#define FPAD 32
#define MTOT (TT*BB)                 // 24000 rows
#define MTILES ((MTOT + 127)/128)    // 188
#define HSTR 1032                    // padded bf16 row stride (2064 B)

typedef unsigned long long u64;

#define CPA_COMMIT() asm volatile("cp.async.commit_group;" ::: "memory")
#define CPA_WAIT(n)  asm volatile("cp.async.wait_group %0;" :: "n"(n) : "memory")

#define SMEM_SWZ(o) ((o) ^ (((o) >> 3) & 0x70))

__device__ __forceinline__ uint32_t smem_u32(const void* p) {
    uint32_t a;
    asm("{ .reg .u64 t; cvta.to.shared.u64 t, %1; cvt.u32.u64 %0, t; }" : "=r"(a) : "l"(p));
    return a;
}

// warp-level bf16 tensor ops (baseline ISA — valid on compute_103 target)
#define LDSM_X4(r0,r1,r2,r3,addr) \
    asm volatile("ldmatrix.sync.aligned.m8n8.x4.shared.b16 {%0,%1,%2,%3}, [%4];" \
        : "=r"(r0), "=r"(r1), "=r"(r2), "=r"(r3) : "r"(addr))
#define LDSM_X2(r0,r1,addr) \
    asm volatile("ldmatrix.sync.aligned.m8n8.x2.shared.b16 {%0,%1}, [%2];" \
        : "=r"(r0), "=r"(r1) : "r"(addr))
#define MMA16816(d,a,b) \
    asm volatile("mma.sync.aligned.m16n8k16.row.col.f32.bf16.bf16.f32 " \
        "{%0,%1,%2,%3}, {%4,%5,%6,%7}, {%8,%9}, {%0,%1,%2,%3};" \
        : "+f"((d)[0]), "+f"((d)[1]), "+f"((d)[2]), "+f"((d)[3]) \
        : "r"((a)[0]), "r"((a)[1]), "r"((a)[2]), "r"((a)[3]), \
          "r"((b)[0]), "r"((b)[1]))

// -------- scratch (device globals: no allocation allowed) --------
__device__ float g_wh[NTOT];
__device__ float g_wz[NTOT];
__device__ float g_h0[NTOT];
__device__ __nv_bfloat16 g_hTh[BB*HH];   // h broadcast, bf16 hi
__device__ __nv_bfloat16 g_hTl[BB*HH];   // h broadcast, bf16 lo
__device__ int   g_flags[2*GRID_SCAN*FPAD];
__device__ __nv_bfloat16 g_ahi[MTOT*HH];
__device__ __nv_bfloat16 g_alo[MTOT*HH];
__device__ __nv_bfloat16 g_whi[HH*HH];
__device__ __nv_bfloat16 g_wlo[HH*HH];

// =================================================================
__global__ void init_kernel(const int* __restrict__ x_len,
                            float* __restrict__ out, int out_size)
{
    int i = blockIdx.x * blockDim.x + threadIdx.x;
    if (i < 2*GRID_SCAN*FPAD) g_flags[i] = 0;
    if (out_size >= NTOT + BB && i < BB) out[NTOT + i] = (float)x_len[i];
}

// =================================================================
// fp32 -> (bf16 hi, bf16 lo) split, vectorized
// =================================================================
__global__ void split_kernel(const float* __restrict__ src,
                             __nv_bfloat16* __restrict__ hi,
                             __nv_bfloat16* __restrict__ lo, int n)
{
    int i = (blockIdx.x * blockDim.x + threadIdx.x) * 4;
    int stride = gridDim.x * blockDim.x * 4;
    for (; i < n; i += stride) {
        float4 x = *(const float4*)(src + i);
        __nv_bfloat16 h0 = __float2bfloat16(x.x), h1 = __float2bfloat16(x.y);
        __nv_bfloat16 h2 = __float2bfloat16(x.z), h3 = __float2bfloat16(x.w);
        __nv_bfloat162 H0; H0.x = h0; H0.y = h1;
        __nv_bfloat162 H1; H1.x = h2; H1.y = h3;
        *(__nv_bfloat162*)(hi + i)     = H0;
        *(__nv_bfloat162*)(hi + i + 2) = H1;
        __nv_bfloat162 L0, L1;
        L0.x = __float2bfloat16(x.x - __bfloat162float(h0));
        L0.y = __float2bfloat16(x.y - __bfloat162float(h1));
        L1.x = __float2bfloat16(x.z - __bfloat162float(h2));
        L1.y = __float2bfloat16(x.w - __bfloat162float(h3));
        *(__nv_bfloat162*)(lo + i)     = L0;
        *(__nv_bfloat162*)(lo + i + 2) = L1;
    }
}

// =================================================================
// split-bf16 tensor GEMM (R12, unchanged) + fused eval BN.
// =================================================================
__global__ void __launch_bounds__(256) tc_gemm_kernel(
    const __nv_bfloat16* __restrict__ Ahi, const __nv_bfloat16* __restrict__ Alo,
    const __nv_bfloat16* __restrict__ Whi, const __nv_bfloat16* __restrict__ Wlo,
    float* __restrict__ C,
    const float* __restrict__ gam, const float* __restrict__ bet,
    const float* __restrict__ mu,  const float* __restrict__ var,
    int K, int Mtot)
{
    __shared__ __align__(128) __nv_bfloat16 As[128*64];
    __shared__ __align__(128) __nv_bfloat16 Bs[128*64];
    __shared__ float s_sc[128], s_sh[128];

    uint32_t a_s = smem_u32(As);
    uint32_t b_s = smem_u32(Bs);

    int tid  = threadIdx.x;
    int w    = tid >> 5, lane = tid & 31;
    int wm   = w & 1;
    int wn   = w >> 1;
    int m0   = blockIdx.y * 128;
    int n0   = blockIdx.x * 128;

    if (tid < 128) {
        int n = n0 + tid;
        float inv = rsqrtf(var[n] + EPSF);
        float sc = gam[n] * inv;
        s_sc[tid] = sc;
        s_sh[tid] = bet[n] - mu[n] * sc;
    }

    float acc[4][4][4];
    #pragma unroll
    for (int i = 0; i < 4; i++)
        #pragma unroll
        for (int j = 0; j < 4; j++)
            #pragma unroll
            for (int q = 0; q < 4; q++) acc[i][j][q] = 0.f;

    uint32_t a_off0 = (uint32_t)((wm*64 + (lane & 15)) << 7) + ((lane >> 4) << 4);
    uint32_t b_off0 = (uint32_t)((wn*32 + (lane & 7)) << 7) + (((lane >> 3) & 1) << 4);

    int nslab = K >> 6;

    for (int pass = 0; pass < 3; pass++) {
        const __nv_bfloat16* Ap = (pass == 2) ? Alo : Ahi;
        const __nv_bfloat16* Bp = (pass == 1) ? Wlo : Whi;
        for (int ks = 0; ks < nslab; ks++) {
            #pragma unroll
            for (int i = 0; i < 4; i++) {
                int idx = tid + (i << 8);
                int r = idx >> 3, g = idx & 7;
                uint32_t dsw = SMEM_SWZ((uint32_t)((r << 7) + (g << 4)));
                int arow = m0 + r;
                int sz = (arow < Mtot) ? 16 : 0;
                if (arow >= Mtot) arow = Mtot - 1;
                const __nv_bfloat16* sa = Ap + (size_t)arow*K + (ks << 6) + (g << 3);
                asm volatile("cp.async.cg.shared.global [%0], [%1], 16, %2;"
                             :: "r"(a_s + dsw), "l"(sa), "r"(sz) : "memory");
                const __nv_bfloat16* sb = Bp + (size_t)(n0 + r)*K + (ks << 6) + (g << 3);
                asm volatile("cp.async.cg.shared.global [%0], [%1], 16;"
                             :: "r"(b_s + dsw), "l"(sb) : "memory");
            }
            CPA_COMMIT();
            CPA_WAIT(0);
            __syncthreads();

            #pragma unroll
            for (int kst = 0; kst < 4; kst++) {
                uint32_t af[4][4], bf[4][2];
                #pragma unroll
                for (int i = 0; i < 4; i++) {
                    uint32_t off = a_off0 + (uint32_t)(i << 11) + (uint32_t)(kst << 5);
                    LDSM_X4(af[i][0], af[i][1], af[i][2], af[i][3], a_s + SMEM_SWZ(off));
                }
                #pragma unroll
                for (int j = 0; j < 4; j++) {
                    uint32_t off = b_off0 + (uint32_t)(j << 10) + (uint32_t)(kst << 5);
                    LDSM_X2(bf[j][0], bf[j][1], b_s + SMEM_SWZ(off));
                }
                #pragma unroll
                for (int i = 0; i < 4; i++)
                    #pragma unroll
                    for (int j = 0; j < 4; j++)
                        MMA16816(acc[i][j], af[i], bf[j]);
            }
            __syncthreads();
        }
    }

    #pragma unroll
    for (int i = 0; i < 4; i++) {
        int r0 = m0 + wm*64 + i*16 + (lane >> 2);
        #pragma unroll
        for (int j = 0; j < 4; j++) {
            int c = wn*32 + j*8 + 2*(lane & 3);
            float sc0 = s_sc[c], sc1 = s_sc[c+1];
            float sh0 = s_sh[c], sh1 = s_sh[c+1];
            if (r0 < Mtot) {
                float2 v;
                v.x = acc[i][j][0] * sc0 + sh0;
                v.y = acc[i][j][1] * sc1 + sh1;
                *(float2*)(C + (size_t)r0*HH + n0 + c) = v;
            }
            if (r0 + 8 < Mtot) {
                float2 v;
                v.x = acc[i][j][2] * sc0 + sh0;
                v.y = acc[i][j][3] * sc1 + sh1;
                *(float2*)(C + (size_t)(r0+8)*HH + n0 + c) = v;
            }
        }
    }
}

// =================================================================
// persistent liGRU scan v7: split-bf16 mma.sync step matmul.
// CTA owns 8 cols; output tile = one m16n8 (16 batch x 8 cols) per
// gate.  Warp (g = w>>2: z/a gate, s = w&3: 256-k slice): U B-frags
// register-stationary (ldmatrix'd once), per step 16 ksteps x
// (2 LDSM.x4 + 3 MMA) with fp32 acc; 4-slice partial reduce in smem;
// gate on 64 threads with REGISTER-carried h_old; h exchanged as
// bf16 hi/lo via R9's 2-chunk cp.async pipeline + flag barrier.
// =================================================================
__global__ void __launch_bounds__(256, 1) scan_kernel(
    const float* __restrict__ WH, const float* __restrict__ WZ,
    const float* __restrict__ Uh, const float* __restrict__ Uz,
    float* __restrict__ Hout,
    __nv_bfloat16* __restrict__ hTh, __nv_bfloat16* __restrict__ hTl,
    int* __restrict__ flags)
{
    extern __shared__ unsigned char smem_raw[];
    __nv_bfloat16* h_hi = (__nv_bfloat16*)smem_raw;        // [16][HSTR]
    __nv_bfloat16* h_lo = h_hi + 16*HSTR;                  // [16][HSTR]
    float* red2 = (float*)(h_lo + 16*HSTR);                // [8][128]
    uint32_t hi_s = smem_u32(h_hi), lo_s = smem_u32(h_lo);

    int tid = threadIdx.x, w = tid >> 5, lane = tid & 31;
    int g = w >> 2;            // 0 = z-gate, 1 = a-gate
    int s = w & 3;             // k-slice (256 wide)
    int j0 = blockIdx.x * 8;

    // ---- stage U as bf16 hi/lo into smem (reusing h buffers) ----
    // h_hi rows 0-7: Uz-hi, rows 8-15: Uz-lo
    // h_lo rows 0-7: Uh-hi, rows 8-15: Uh-lo
    for (int idx = tid; idx < 8*HH; idx += 256) {
        int r = idx >> 10, k = idx & (HH-1);
        float vz = Uz[(size_t)(j0+r)*HH + k];
        float vh = Uh[(size_t)(j0+r)*HH + k];
        __nv_bfloat16 zh = __float2bfloat16(vz);
        __nv_bfloat16 hh = __float2bfloat16(vh);
        h_hi[r*HSTR + k]     = zh;
        h_hi[(r+8)*HSTR + k] = __float2bfloat16(vz - __bfloat162float(zh));
        h_lo[r*HSTR + k]     = hh;
        h_lo[(r+8)*HSTR + k] = __float2bfloat16(vh - __bfloat162float(hh));
    }
    __syncthreads();

    // ---- register-stationary U B-frags ----
    uint32_t ufh[16][2], ufl[16][2];
    {
        uint32_t base = g ? lo_s : hi_s;
        uint32_t rowoff = (uint32_t)((lane & 7)*2064) + (uint32_t)(((lane >> 3) & 1)*16);
        #pragma unroll
        for (int kst = 0; kst < 16; kst++) {
            uint32_t kb = (uint32_t)((s*256 + kst*16)*2);
            LDSM_X2(ufh[kst][0], ufh[kst][1], base + rowoff + kb);
            LDSM_X2(ufl[kst][0], ufl[kst][1], base + 8*2064 + rowoff + kb);
        }
    }
    __syncthreads();

    // ---- zero h smem (h_{-1} = 0) ----
    {
        uint4 z4; z4.x = z4.y = z4.z = z4.w = 0u;
        for (int idx = tid; idx < (2*16*HSTR*2)/16; idx += 256)
            ((uint4*)smem_raw)[idx] = z4;
    }
    __syncthreads();

    // A-frag lane address (h tile: rows = batch, k-contiguous)
    uint32_t a_off = (uint32_t)((lane & 15)*2064) + (uint32_t)((lane >> 4)*16);

    // gate thread mapping: tid<64 -> (b, col-pair jp)
    int b_o = tid & 15, jp = tid >> 4;
    int lr  = ((b_o & 7)*4 + jp)*4 + ((b_o >> 3) ? 2 : 0);
    bool is_gate = (tid < 64);
    int jg = j0 + 2*jp;
    float hold0 = 0.f, hold1 = 0.f;

    for (int t = 0; t < TT; t++) {
        float2 wz2 = make_float2(0.f, 0.f), wh2 = wz2;
        size_t ob = 0;
        if (is_gate) {
            ob = ((size_t)t*BB + b_o)*HH + jg;
            wz2 = *(const float2*)(WZ + ob);
            wh2 = *(const float2*)(WH + ob);
        }

        float acc[4] = {0.f, 0.f, 0.f, 0.f};

        CPA_WAIT(1);
        __syncthreads();
        if (s < 2) {                       // k < 512 (chunk0 resident)
            #pragma unroll
            for (int kst = 0; kst < 16; kst++) {
                uint32_t kb = (uint32_t)((s*256 + kst*16)*2);
                uint32_t ah[4], al[4];
                LDSM_X4(ah[0], ah[1], ah[2], ah[3], hi_s + a_off + kb);
                LDSM_X4(al[0], al[1], al[2], al[3], lo_s + a_off + kb);
                MMA16816(acc, ah, ufh[kst]);
                MMA16816(acc, ah, ufl[kst]);
                MMA16816(acc, al, ufh[kst]);
            }
        }
        CPA_WAIT(0);
        __syncthreads();
        if (s >= 2) {                      // k >= 512 (chunk1 resident)
            #pragma unroll
            for (int kst = 0; kst < 16; kst++) {
                uint32_t kb = (uint32_t)((s*256 + kst*16)*2);
                uint32_t ah[4], al[4];
                LDSM_X4(ah[0], ah[1], ah[2], ah[3], hi_s + a_off + kb);
                LDSM_X4(al[0], al[1], al[2], al[3], lo_s + a_off + kb);
                MMA16816(acc, ah, ufh[kst]);
                MMA16816(acc, ah, ufl[kst]);
                MMA16816(acc, al, ufh[kst]);
            }
        }

        // ---- partial write: red2[w][lane*4..+3] ----
        *(float4*)(red2 + w*128 + lane*4) = *(float4*)acc;
        __syncthreads();

        // ---- reduce 4 slices + gate (64 threads) ----
        if (is_gate) {
            const float* rz = red2 + lr;           // z-gate: warps 0-3
            const float* ra = red2 + 4*128 + lr;   // a-gate: warps 4-7
            float z0 = 0.f, z1 = 0.f, a0 = 0.f, a1 = 0.f;
            #pragma unroll
            for (int ss = 0; ss < 4; ss++) {
                float2 vz = *(const float2*)(rz + ss*128);
                float2 va = *(const float2*)(ra + ss*128);
                z0 += vz.x; z1 += vz.y;
                a0 += va.x; a1 += va.y;
            }
            float zt0 = 1.f / (1.f + __expf(-(wz2.x + z0)));
            float zt1 = 1.f / (1.f + __expf(-(wz2.y + z1)));
            float hc0 = fmaxf(wh2.x + a0, 0.f) * KEEPF;
            float hc1 = fmaxf(wh2.y + a1, 0.f) * KEEPF;
            float hn0 = zt0*hold0 + (1.f - zt0)*hc0;
            float hn1 = zt1*hold1 + (1.f - zt1)*hc1;
            hold0 = hn0; hold1 = hn1;
            float2 o; o.x = hn0; o.y = hn1;
            *(float2*)(Hout + ob) = o;
            __nv_bfloat162 hi2, lo2;
            hi2.x = __float2bfloat16(hn0);
            hi2.y = __float2bfloat16(hn1);
            lo2.x = __float2bfloat16(hn0 - __bfloat162float(hi2.x));
            lo2.y = __float2bfloat16(hn1 - __bfloat162float(hi2.y));
            *(__nv_bfloat162*)(hTh + b_o*HH + jg) = hi2;
            *(__nv_bfloat162*)(hTl + b_o*HH + jg) = lo2;
        }
        __syncthreads();
        if (t == TT-1) break;

        // ---- release/acquire distributed-flag grid barrier (R9) ----
        if (tid == 0) {
            asm volatile("st.release.gpu.global.s32 [%0], %1;"
                         :: "l"(flags + blockIdx.x*FPAD), "r"(t+1) : "memory");
        }
        if (tid < GRID_SCAN) {
            const int* fp = flags + tid*FPAD;
            int v;
            do {
                asm volatile("ld.acquire.gpu.global.s32 %0, [%1];"
                             : "=r"(v) : "l"(fp) : "memory");
            } while (v <= t);
        }
        __syncthreads();

        // ---- issue pipelined h reload: 2 k-chunks x (hi + lo) ----
        #pragma unroll
        for (int i = 0; i < 4; i++) {
            int idx = tid + (i << 8);              // 0..1023
            int b = idx >> 6, kq = idx & 63;       // 16B granule (8 bf16)
            uint32_t dofs = (uint32_t)(b*2064 + kq*16);
            const __nv_bfloat16* s0p = hTh + b*HH + kq*8;
            const __nv_bfloat16* s1p = hTl + b*HH + kq*8;
            asm volatile("cp.async.cg.shared.global [%0], [%1], 16;"
                         :: "r"(hi_s + dofs), "l"(s0p) : "memory");
            asm volatile("cp.async.cg.shared.global [%0], [%1], 16;"
                         :: "r"(lo_s + dofs), "l"(s1p) : "memory");
        }
        CPA_COMMIT();
        #pragma unroll
        for (int i = 0; i < 4; i++) {
            int idx = tid + (i << 8);
            int b = idx >> 6, kq = (idx & 63) + 64;
            uint32_t dofs = (uint32_t)(b*2064 + kq*16);
            const __nv_bfloat16* s0p = hTh + b*HH + kq*8;
            const __nv_bfloat16* s1p = hTl + b*HH + kq*8;
            asm volatile("cp.async.cg.shared.global [%0], [%1], 16;"
                         :: "r"(hi_s + dofs), "l"(s0p) : "memory");
            asm volatile("cp.async.cg.shared.global [%0], [%1], 16;"
                         :: "r"(lo_s + dofs), "l"(s1p) : "memory");
        }
        CPA_COMMIT();
    }
}

// =================================================================
extern "C" void kernel_launch(void* const* d_in, const int* in_sizes, int n_in,
                              void* d_out, int out_size)
{
    const float* x     = (const float*)d_in[0];
    const int*   x_len = (const int*)  d_in[1];
    const float* whW0  = (const float*)d_in[2];
    const float* wzW0  = (const float*)d_in[3];
    const float* uhW0  = (const float*)d_in[4];
    const float* uzW0  = (const float*)d_in[5];
    const float* bnh_g0 = (const float*)d_in[6];
    const float* bnh_b0 = (const float*)d_in[7];
    const float* bnh_m0 = (const float*)d_in[8];
    const float* bnh_v0 = (const float*)d_in[9];
    const float* bnz_g0 = (const float*)d_in[10];
    const float* bnz_b0 = (const float*)d_in[11];
    const float* bnz_m0 = (const float*)d_in[12];
    const float* bnz_v0 = (const float*)d_in[13];
    const float* whW1  = (const float*)d_in[14];
    const float* wzW1  = (const float*)d_in[15];
    const float* uhW1  = (const float*)d_in[16];
    const float* uzW1  = (const float*)d_in[17];
    const float* bnh_g1 = (const float*)d_in[18];
    const float* bnh_b1 = (const float*)d_in[19];
    const float* bnh_m1 = (const float*)d_in[20];
    const float* bnh_v1 = (const float*)d_in[21];
    const float* bnz_g1 = (const float*)d_in[22];
    const float* bnz_b1 = (const float*)d_in[23];
    const float* bnz_m1 = (const float*)d_in[24];
    const float* bnz_v1 = (const float*)d_in[25];

    float* out = (float*)d_out;

    float *p_wh, *p_wz, *p_h0; int* p_fl;
    __nv_bfloat16 *p_ahi, *p_alo, *p_whi, *p_wlo, *p_hTh, *p_hTl;
    cudaGetSymbolAddress((void**)&p_wh, g_wh);
    cudaGetSymbolAddress((void**)&p_wz, g_wz);
    cudaGetSymbolAddress((void**)&p_h0, g_h0);
    cudaGetSymbolAddress((void**)&p_fl, g_flags);
    cudaGetSymbolAddress((void**)&p_ahi, g_ahi);
    cudaGetSymbolAddress((void**)&p_alo, g_alo);
    cudaGetSymbolAddress((void**)&p_whi, g_whi);
    cudaGetSymbolAddress((void**)&p_wlo, g_wlo);
    cudaGetSymbolAddress((void**)&p_hTh, g_hTh);
    cudaGetSymbolAddress((void**)&p_hTl, g_hTl);

    int smem_scan = 2*16*HSTR*2 + 8*128*4;   // 66048 + 4096 = 70144 B
    cudaFuncSetAttribute(scan_kernel,
        cudaFuncAttributeMaxDynamicSharedMemorySize, smem_scan);

    init_kernel<<<32, 256>>>(x_len, out, out_size);

    dim3 gg(HH/128, MTILES);     // (8, 188)

    // ---- layer 0 (K = 512) ----
    split_kernel<<<592, 256>>>(x, p_ahi, p_alo, MTOT*DD);
    split_kernel<<<592, 256>>>(whW0, p_whi, p_wlo, HH*DD);
    tc_gemm_kernel<<<gg, 256>>>(p_ahi, p_alo, p_whi, p_wlo, p_wh,
                                bnh_g0, bnh_b0, bnh_m0, bnh_v0, DD, MTOT);
    split_kernel<<<592, 256>>>(wzW0, p_whi, p_wlo, HH*DD);
    tc_gemm_kernel<<<gg, 256>>>(p_ahi, p_alo, p_whi, p_wlo, p_wz,
                                bnz_g0, bnz_b0, bnz_m0, bnz_v0, DD, MTOT);
    scan_kernel<<<GRID_SCAN, 256, smem_scan>>>(p_wh, p_wz, uhW0, uzW0, p_h0,
                                               p_hTh, p_hTl, p_fl);

    // ---- layer 1 (K = 1024) ----
    split_kernel<<<592, 256>>>(p_h0, p_ahi, p_alo, MTOT*HH);
    split_kernel<<<592, 256>>>(whW1, p_whi, p_wlo, HH*HH);
    tc_gemm_kernel<<<gg, 256>>>(p_ahi, p_alo, p_whi, p_wlo, p_wh,
                                bnh_g1, bnh_b1, bnh_m1, bnh_v1, HH, MTOT);
    split_kernel<<<592, 256>>>(wzW1, p_whi, p_wlo, HH*HH);
    tc_gemm_kernel<<<gg, 256>>>(p_ahi, p_alo, p_whi, p_wlo, p_wz,
                                bnz_g1, bnz_b1, bnz_m1, bnz_v1, HH, MTOT);
    scan_kernel<<<GRID_SCAN, 256, smem_scan>>>(p_wh, p_wz, uhW1, uzW1, out,
                                               p_hTh, p_hTl,
                                               p_fl + GRID_SCAN*FPAD);
}

// round 14
// speedup vs baseline: 1.0822x; 1.0822x over previous
#include <cuda_runtime.h>
#include <cuda_bf16.h>
#include <cstdint>
#include <math.h>

#define TT 1500
#define BB 16
#define DD 512
#define HH 1024
#define KEEPF 0.8f
#define EPSF 1e-5f
#define NTOT (TT*BB*HH)
#define GRID_SCAN 128
#define FPAD 32
#define MTOT (TT*BB)                 // 24000 rows
#define MTILES ((MTOT + 127)/128)    // 188
#define HSTR 1032                    // padded bf16 row stride (2064 B)

typedef unsigned long long u64;

#define CPA_COMMIT() asm volatile("cp.async.commit_group;" ::: "memory")
#define CPA_WAIT(n)  asm volatile("cp.async.wait_group %0;" :: "n"(n) : "memory")

#define SMEM_SWZ(o) ((o) ^ (((o) >> 3) & 0x70))

__device__ __forceinline__ uint32_t smem_u32(const void* p) {
    uint32_t a;
    asm("{ .reg .u64 t; cvta.to.shared.u64 t, %1; cvt.u32.u64 %0, t; }" : "=r"(a) : "l"(p));
    return a;
}

// warp-level bf16 tensor ops (baseline ISA — valid on compute_103 target)
#define LDSM_X4(r0,r1,r2,r3,addr) \
    asm volatile("ldmatrix.sync.aligned.m8n8.x4.shared.b16 {%0,%1,%2,%3}, [%4];" \
        : "=r"(r0), "=r"(r1), "=r"(r2), "=r"(r3) : "r"(addr))
#define LDSM_X2(r0,r1,addr) \
    asm volatile("ldmatrix.sync.aligned.m8n8.x2.shared.b16 {%0,%1}, [%2];" \
        : "=r"(r0), "=r"(r1) : "r"(addr))
#define MMA16816(d,a,b) \
    asm volatile("mma.sync.aligned.m16n8k16.row.col.f32.bf16.bf16.f32 " \
        "{%0,%1,%2,%3}, {%4,%5,%6,%7}, {%8,%9}, {%0,%1,%2,%3};" \
        : "+f"((d)[0]), "+f"((d)[1]), "+f"((d)[2]), "+f"((d)[3]) \
        : "r"((a)[0]), "r"((a)[1]), "r"((a)[2]), "r"((a)[3]), \
          "r"((b)[0]), "r"((b)[1]))

// -------- scratch (device globals: no allocation allowed) --------
__device__ float g_wh[NTOT];
__device__ float g_wz[NTOT];
__device__ float g_h0[NTOT];
__device__ __nv_bfloat16 g_hTh[BB*HH];   // h broadcast, bf16 hi
__device__ __nv_bfloat16 g_hTl[BB*HH];   // h broadcast, bf16 lo
__device__ int   g_flags[2*GRID_SCAN*FPAD];
__device__ __nv_bfloat16 g_ahi[MTOT*HH];
__device__ __nv_bfloat16 g_alo[MTOT*HH];
__device__ __nv_bfloat16 g_whi[HH*HH];
__device__ __nv_bfloat16 g_wlo[HH*HH];

// =================================================================
__global__ void init_kernel(const int* __restrict__ x_len,
                            float* __restrict__ out, int out_size)
{
    int i = blockIdx.x * blockDim.x + threadIdx.x;
    if (i < 2*GRID_SCAN*FPAD) g_flags[i] = 0;
    if (out_size >= NTOT + BB && i < BB) out[NTOT + i] = (float)x_len[i];
}

// =================================================================
// fp32 -> (bf16 hi, bf16 lo) split, vectorized
// =================================================================
__global__ void split_kernel(const float* __restrict__ src,
                             __nv_bfloat16* __restrict__ hi,
                             __nv_bfloat16* __restrict__ lo, int n)
{
    int i = (blockIdx.x * blockDim.x + threadIdx.x) * 4;
    int stride = gridDim.x * blockDim.x * 4;
    for (; i < n; i += stride) {
        float4 x = *(const float4*)(src + i);
        __nv_bfloat16 h0 = __float2bfloat16(x.x), h1 = __float2bfloat16(x.y);
        __nv_bfloat16 h2 = __float2bfloat16(x.z), h3 = __float2bfloat16(x.w);
        __nv_bfloat162 H0; H0.x = h0; H0.y = h1;
        __nv_bfloat162 H1; H1.x = h2; H1.y = h3;
        *(__nv_bfloat162*)(hi + i)     = H0;
        *(__nv_bfloat162*)(hi + i + 2) = H1;
        __nv_bfloat162 L0, L1;
        L0.x = __float2bfloat16(x.x - __bfloat162float(h0));
        L0.y = __float2bfloat16(x.y - __bfloat162float(h1));
        L1.x = __float2bfloat16(x.z - __bfloat162float(h2));
        L1.y = __float2bfloat16(x.w - __bfloat162float(h3));
        *(__nv_bfloat162*)(lo + i)     = L0;
        *(__nv_bfloat162*)(lo + i + 2) = L1;
    }
}

// =================================================================
// split-bf16 tensor GEMM (R12, unchanged) + fused eval BN.
// =================================================================
__global__ void __launch_bounds__(256) tc_gemm_kernel(
    const __nv_bfloat16* __restrict__ Ahi, const __nv_bfloat16* __restrict__ Alo,
    const __nv_bfloat16* __restrict__ Whi, const __nv_bfloat16* __restrict__ Wlo,
    float* __restrict__ C,
    const float* __restrict__ gam, const float* __restrict__ bet,
    const float* __restrict__ mu,  const float* __restrict__ var,
    int K, int Mtot)
{
    __shared__ __align__(128) __nv_bfloat16 As[128*64];
    __shared__ __align__(128) __nv_bfloat16 Bs[128*64];
    __shared__ float s_sc[128], s_sh[128];

    uint32_t a_s = smem_u32(As);
    uint32_t b_s = smem_u32(Bs);

    int tid  = threadIdx.x;
    int w    = tid >> 5, lane = tid & 31;
    int wm   = w & 1;
    int wn   = w >> 1;
    int m0   = blockIdx.y * 128;
    int n0   = blockIdx.x * 128;

    if (tid < 128) {
        int n = n0 + tid;
        float inv = rsqrtf(var[n] + EPSF);
        float sc = gam[n] * inv;
        s_sc[tid] = sc;
        s_sh[tid] = bet[n] - mu[n] * sc;
    }

    float acc[4][4][4];
    #pragma unroll
    for (int i = 0; i < 4; i++)
        #pragma unroll
        for (int j = 0; j < 4; j++)
            #pragma unroll
            for (int q = 0; q < 4; q++) acc[i][j][q] = 0.f;

    uint32_t a_off0 = (uint32_t)((wm*64 + (lane & 15)) << 7) + ((lane >> 4) << 4);
    uint32_t b_off0 = (uint32_t)((wn*32 + (lane & 7)) << 7) + (((lane >> 3) & 1) << 4);

    int nslab = K >> 6;

    for (int pass = 0; pass < 3; pass++) {
        const __nv_bfloat16* Ap = (pass == 2) ? Alo : Ahi;
        const __nv_bfloat16* Bp = (pass == 1) ? Wlo : Whi;
        for (int ks = 0; ks < nslab; ks++) {
            #pragma unroll
            for (int i = 0; i < 4; i++) {
                int idx = tid + (i << 8);
                int r = idx >> 3, g = idx & 7;
                uint32_t dsw = SMEM_SWZ((uint32_t)((r << 7) + (g << 4)));
                int arow = m0 + r;
                int sz = (arow < Mtot) ? 16 : 0;
                if (arow >= Mtot) arow = Mtot - 1;
                const __nv_bfloat16* sa = Ap + (size_t)arow*K + (ks << 6) + (g << 3);
                asm volatile("cp.async.cg.shared.global [%0], [%1], 16, %2;"
                             :: "r"(a_s + dsw), "l"(sa), "r"(sz) : "memory");
                const __nv_bfloat16* sb = Bp + (size_t)(n0 + r)*K + (ks << 6) + (g << 3);
                asm volatile("cp.async.cg.shared.global [%0], [%1], 16;"
                             :: "r"(b_s + dsw), "l"(sb) : "memory");
            }
            CPA_COMMIT();
            CPA_WAIT(0);
            __syncthreads();

            #pragma unroll
            for (int kst = 0; kst < 4; kst++) {
                uint32_t af[4][4], bf[4][2];
                #pragma unroll
                for (int i = 0; i < 4; i++) {
                    uint32_t off = a_off0 + (uint32_t)(i << 11) + (uint32_t)(kst << 5);
                    LDSM_X4(af[i][0], af[i][1], af[i][2], af[i][3], a_s + SMEM_SWZ(off));
                }
                #pragma unroll
                for (int j = 0; j < 4; j++) {
                    uint32_t off = b_off0 + (uint32_t)(j << 10) + (uint32_t)(kst << 5);
                    LDSM_X2(bf[j][0], bf[j][1], b_s + SMEM_SWZ(off));
                }
                #pragma unroll
                for (int i = 0; i < 4; i++)
                    #pragma unroll
                    for (int j = 0; j < 4; j++)
                        MMA16816(acc[i][j], af[i], bf[j]);
            }
            __syncthreads();
        }
    }

    #pragma unroll
    for (int i = 0; i < 4; i++) {
        int r0 = m0 + wm*64 + i*16 + (lane >> 2);
        #pragma unroll
        for (int j = 0; j < 4; j++) {
            int c = wn*32 + j*8 + 2*(lane & 3);
            float sc0 = s_sc[c], sc1 = s_sc[c+1];
            float sh0 = s_sh[c], sh1 = s_sh[c+1];
            if (r0 < Mtot) {
                float2 v;
                v.x = acc[i][j][0] * sc0 + sh0;
                v.y = acc[i][j][1] * sc1 + sh1;
                *(float2*)(C + (size_t)r0*HH + n0 + c) = v;
            }
            if (r0 + 8 < Mtot) {
                float2 v;
                v.x = acc[i][j][2] * sc0 + sh0;
                v.y = acc[i][j][3] * sc1 + sh1;
                *(float2*)(C + (size_t)(r0+8)*HH + n0 + c) = v;
            }
        }
    }
}

// =================================================================
// persistent liGRU scan v8: split-bf16 mma.sync, ALL warps busy in
// BOTH chunk phases + 3 independent accumulators.
// Warp (g = w>>2: z/a gate, s = w&3) covers k in
//   [128s, 128s+128) ∪ [512+128s, 512+128s+128)
// (first half ready with chunk0, second with chunk1).
// =================================================================
__global__ void __launch_bounds__(256, 1) scan_kernel(
    const float* __restrict__ WH, const float* __restrict__ WZ,
    const float* __restrict__ Uh, const float* __restrict__ Uz,
    float* __restrict__ Hout,
    __nv_bfloat16* __restrict__ hTh, __nv_bfloat16* __restrict__ hTl,
    int* __restrict__ flags)
{
    extern __shared__ unsigned char smem_raw[];
    __nv_bfloat16* h_hi = (__nv_bfloat16*)smem_raw;        // [16][HSTR]
    __nv_bfloat16* h_lo = h_hi + 16*HSTR;                  // [16][HSTR]
    float* red2 = (float*)(h_lo + 16*HSTR);                // [8][128]
    uint32_t hi_s = smem_u32(h_hi), lo_s = smem_u32(h_lo);

    int tid = threadIdx.x, w = tid >> 5, lane = tid & 31;
    int g = w >> 2;            // 0 = z-gate, 1 = a-gate
    int s = w & 3;             // k-slice within each chunk (128 wide)
    int j0 = blockIdx.x * 8;

    // kst kk -> global k base: kk<8 in chunk0, kk>=8 in chunk1
    // k(kk) = (kk<8 ? 0 : 512) + s*128 + (kk&7)*16

    // ---- stage U as bf16 hi/lo into smem (reusing h buffers) ----
    for (int idx = tid; idx < 8*HH; idx += 256) {
        int r = idx >> 10, k = idx & (HH-1);
        float vz = Uz[(size_t)(j0+r)*HH + k];
        float vh = Uh[(size_t)(j0+r)*HH + k];
        __nv_bfloat16 zh = __float2bfloat16(vz);
        __nv_bfloat16 hh = __float2bfloat16(vh);
        h_hi[r*HSTR + k]     = zh;
        h_hi[(r+8)*HSTR + k] = __float2bfloat16(vz - __bfloat162float(zh));
        h_lo[r*HSTR + k]     = hh;
        h_lo[(r+8)*HSTR + k] = __float2bfloat16(vh - __bfloat162float(hh));
    }
    __syncthreads();

    // ---- register-stationary U B-frags (new k mapping) ----
    uint32_t ufh[16][2], ufl[16][2];
    {
        uint32_t base = g ? lo_s : hi_s;
        uint32_t rowoff = (uint32_t)((lane & 7)*2064) + (uint32_t)(((lane >> 3) & 1)*16);
        #pragma unroll
        for (int kk = 0; kk < 16; kk++) {
            int kglob = ((kk < 8) ? 0 : 512) + s*128 + (kk & 7)*16;
            uint32_t kb = (uint32_t)(kglob*2);
            LDSM_X2(ufh[kk][0], ufh[kk][1], base + rowoff + kb);
            LDSM_X2(ufl[kk][0], ufl[kk][1], base + 8*2064 + rowoff + kb);
        }
    }
    __syncthreads();

    // ---- zero h smem (h_{-1} = 0) ----
    {
        uint4 z4; z4.x = z4.y = z4.z = z4.w = 0u;
        for (int idx = tid; idx < (2*16*HSTR*2)/16; idx += 256)
            ((uint4*)smem_raw)[idx] = z4;
    }
    __syncthreads();

    // A-frag lane address (h tile: rows = batch, k-contiguous)
    uint32_t a_off = (uint32_t)((lane & 15)*2064) + (uint32_t)((lane >> 4)*16);

    // gate thread mapping (identical to R13 — verified correct)
    int b_o = tid & 15, jp = tid >> 4;
    int lr  = ((b_o & 7)*4 + jp)*4 + ((b_o >> 3) ? 2 : 0);
    bool is_gate = (tid < 64);
    int jg = j0 + 2*jp;
    float hold0 = 0.f, hold1 = 0.f;

    for (int t = 0; t < TT; t++) {
        float2 wz2 = make_float2(0.f, 0.f), wh2 = wz2;
        size_t ob = 0;
        if (is_gate) {
            ob = ((size_t)t*BB + b_o)*HH + jg;
            wz2 = *(const float2*)(WZ + ob);
            wh2 = *(const float2*)(WH + ob);
        }

        float acc0[4] = {0.f,0.f,0.f,0.f};
        float acc1[4] = {0.f,0.f,0.f,0.f};
        float acc2[4] = {0.f,0.f,0.f,0.f};

        // ---- phase 0: chunk0 resident, ksteps 0..7 (all warps) ----
        CPA_WAIT(1);
        __syncthreads();
        #pragma unroll
        for (int kk = 0; kk < 8; kk++) {
            uint32_t kb = (uint32_t)((s*128 + kk*16)*2);
            uint32_t ah[4], al[4];
            LDSM_X4(ah[0], ah[1], ah[2], ah[3], hi_s + a_off + kb);
            LDSM_X4(al[0], al[1], al[2], al[3], lo_s + a_off + kb);
            MMA16816(acc0, ah, ufh[kk]);
            MMA16816(acc1, ah, ufl[kk]);
            MMA16816(acc2, al, ufh[kk]);
        }
        // ---- phase 1: chunk1 resident, ksteps 8..15 ----
        CPA_WAIT(0);
        __syncthreads();
        #pragma unroll
        for (int kk = 8; kk < 16; kk++) {
            uint32_t kb = (uint32_t)((512 + s*128 + (kk-8)*16)*2);
            uint32_t ah[4], al[4];
            LDSM_X4(ah[0], ah[1], ah[2], ah[3], hi_s + a_off + kb);
            LDSM_X4(al[0], al[1], al[2], al[3], lo_s + a_off + kb);
            MMA16816(acc0, ah, ufh[kk]);
            MMA16816(acc1, ah, ufl[kk]);
            MMA16816(acc2, al, ufh[kk]);
        }
        #pragma unroll
        for (int q = 0; q < 4; q++) acc0[q] += acc1[q] + acc2[q];

        // ---- partial write: red2[w][lane*4..+3] ----
        *(float4*)(red2 + w*128 + lane*4) = *(float4*)acc0;
        __syncthreads();

        // ---- reduce 4 slices + gate (64 threads) ----
        if (is_gate) {
            const float* rz = red2 + lr;           // z-gate: warps 0-3
            const float* ra = red2 + 4*128 + lr;   // a-gate: warps 4-7
            float z0 = 0.f, z1 = 0.f, a0 = 0.f, a1 = 0.f;
            #pragma unroll
            for (int ss = 0; ss < 4; ss++) {
                float2 vz = *(const float2*)(rz + ss*128);
                float2 va = *(const float2*)(ra + ss*128);
                z0 += vz.x; z1 += vz.y;
                a0 += va.x; a1 += va.y;
            }
            float zt0 = 1.f / (1.f + __expf(-(wz2.x + z0)));
            float zt1 = 1.f / (1.f + __expf(-(wz2.y + z1)));
            float hc0 = fmaxf(wh2.x + a0, 0.f) * KEEPF;
            float hc1 = fmaxf(wh2.y + a1, 0.f) * KEEPF;
            float hn0 = zt0*hold0 + (1.f - zt0)*hc0;
            float hn1 = zt1*hold1 + (1.f - zt1)*hc1;
            hold0 = hn0; hold1 = hn1;
            float2 o; o.x = hn0; o.y = hn1;
            *(float2*)(Hout + ob) = o;
            __nv_bfloat162 hi2, lo2;
            hi2.x = __float2bfloat16(hn0);
            hi2.y = __float2bfloat16(hn1);
            lo2.x = __float2bfloat16(hn0 - __bfloat162float(hi2.x));
            lo2.y = __float2bfloat16(hn1 - __bfloat162float(hi2.y));
            *(__nv_bfloat162*)(hTh + b_o*HH + jg) = hi2;
            *(__nv_bfloat162*)(hTl + b_o*HH + jg) = lo2;
        }
        __syncthreads();
        if (t == TT-1) break;

        // ---- release/acquire distributed-flag grid barrier ----
        if (tid == 0) {
            asm volatile("st.release.gpu.global.s32 [%0], %1;"
                         :: "l"(flags + blockIdx.x*FPAD), "r"(t+1) : "memory");
        }
        if (tid < GRID_SCAN) {
            const int* fp = flags + tid*FPAD;
            int v;
            do {
                asm volatile("ld.acquire.gpu.global.s32 %0, [%1];"
                             : "=r"(v) : "l"(fp) : "memory");
            } while (v <= t);
        }
        __syncthreads();

        // ---- issue pipelined h reload: 2 k-chunks x (hi + lo) ----
        #pragma unroll
        for (int i = 0; i < 4; i++) {
            int idx = tid + (i << 8);              // 0..1023
            int b = idx >> 6, kq = idx & 63;       // 16B granule (8 bf16)
            uint32_t dofs = (uint32_t)(b*2064 + kq*16);
            const __nv_bfloat16* s0p = hTh + b*HH + kq*8;
            const __nv_bfloat16* s1p = hTl + b*HH + kq*8;
            asm volatile("cp.async.cg.shared.global [%0], [%1], 16;"
                         :: "r"(hi_s + dofs), "l"(s0p) : "memory");
            asm volatile("cp.async.cg.shared.global [%0], [%1], 16;"
                         :: "r"(lo_s + dofs), "l"(s1p) : "memory");
        }
        CPA_COMMIT();
        #pragma unroll
        for (int i = 0; i < 4; i++) {
            int idx = tid + (i << 8);
            int b = idx >> 6, kq = (idx & 63) + 64;
            uint32_t dofs = (uint32_t)(b*2064 + kq*16);
            const __nv_bfloat16* s0p = hTh + b*HH + kq*8;
            const __nv_bfloat16* s1p = hTl + b*HH + kq*8;
            asm volatile("cp.async.cg.shared.global [%0], [%1], 16;"
                         :: "r"(hi_s + dofs), "l"(s0p) : "memory");
            asm volatile("cp.async.cg.shared.global [%0], [%1], 16;"
                         :: "r"(lo_s + dofs), "l"(s1p) : "memory");
        }
        CPA_COMMIT();
    }
}

// =================================================================
extern "C" void kernel_launch(void* const* d_in, const int* in_sizes, int n_in,
                              void* d_out, int out_size)
{
    const float* x     = (const float*)d_in[0];
    const int*   x_len = (const int*)  d_in[1];
    const float* whW0  = (const float*)d_in[2];
    const float* wzW0  = (const float*)d_in[3];
    const float* uhW0  = (const float*)d_in[4];
    const float* uzW0  = (const float*)d_in[5];
    const float* bnh_g0 = (const float*)d_in[6];
    const float* bnh_b0 = (const float*)d_in[7];
    const float* bnh_m0 = (const float*)d_in[8];
    const float* bnh_v0 = (const float*)d_in[9];
    const float* bnz_g0 = (const float*)d_in[10];
    const float* bnz_b0 = (const float*)d_in[11];
    const float* bnz_m0 = (const float*)d_in[12];
    const float* bnz_v0 = (const float*)d_in[13];
    const float* whW1  = (const float*)d_in[14];
    const float* wzW1  = (const float*)d_in[15];
    const float* uhW1  = (const float*)d_in[16];
    const float* uzW1  = (const float*)d_in[17];
    const float* bnh_g1 = (const float*)d_in[18];
    const float* bnh_b1 = (const float*)d_in[19];
    const float* bnh_m1 = (const float*)d_in[20];
    const float* bnh_v1 = (const float*)d_in[21];
    const float* bnz_g1 = (const float*)d_in[22];
    const float* bnz_b1 = (const float*)d_in[23];
    const float* bnz_m1 = (const float*)d_in[24];
    const float* bnz_v1 = (const float*)d_in[25];

    float* out = (float*)d_out;

    float *p_wh, *p_wz, *p_h0; int* p_fl;
    __nv_bfloat16 *p_ahi, *p_alo, *p_whi, *p_wlo, *p_hTh, *p_hTl;
    cudaGetSymbolAddress((void**)&p_wh, g_wh);
    cudaGetSymbolAddress((void**)&p_wz, g_wz);
    cudaGetSymbolAddress((void**)&p_h0, g_h0);
    cudaGetSymbolAddress((void**)&p_fl, g_flags);
    cudaGetSymbolAddress((void**)&p_ahi, g_ahi);
    cudaGetSymbolAddress((void**)&p_alo, g_alo);
    cudaGetSymbolAddress((void**)&p_whi, g_whi);
    cudaGetSymbolAddress((void**)&p_wlo, g_wlo);
    cudaGetSymbolAddress((void**)&p_hTh, g_hTh);
    cudaGetSymbolAddress((void**)&p_hTl, g_hTl);

    int smem_scan = 2*16*HSTR*2 + 8*128*4;   // 66048 + 4096 = 70144 B
    cudaFuncSetAttribute(scan_kernel,
        cudaFuncAttributeMaxDynamicSharedMemorySize, smem_scan);

    init_kernel<<<32, 256>>>(x_len, out, out_size);

    dim3 gg(HH/128, MTILES);     // (8, 188)

    // ---- layer 0 (K = 512) ----
    split_kernel<<<592, 256>>>(x, p_ahi, p_alo, MTOT*DD);
    split_kernel<<<592, 256>>>(whW0, p_whi, p_wlo, HH*DD);
    tc_gemm_kernel<<<gg, 256>>>(p_ahi, p_alo, p_whi, p_wlo, p_wh,
                                bnh_g0, bnh_b0, bnh_m0, bnh_v0, DD, MTOT);
    split_kernel<<<592, 256>>>(wzW0, p_whi, p_wlo, HH*DD);
    tc_gemm_kernel<<<gg, 256>>>(p_ahi, p_alo, p_whi, p_wlo, p_wz,
                                bnz_g0, bnz_b0, bnz_m0, bnz_v0, DD, MTOT);
    scan_kernel<<<GRID_SCAN, 256, smem_scan>>>(p_wh, p_wz, uhW0, uzW0, p_h0,
                                               p_hTh, p_hTl, p_fl);

    // ---- layer 1 (K = 1024) ----
    split_kernel<<<592, 256>>>(p_h0, p_ahi, p_alo, MTOT*HH);
    split_kernel<<<592, 256>>>(whW1, p_whi, p_wlo, HH*HH);
    tc_gemm_kernel<<<gg, 256>>>(p_ahi, p_alo, p_whi, p_wlo, p_wh,
                                bnh_g1, bnh_b1, bnh_m1, bnh_v1, HH, MTOT);
    split_kernel<<<592, 256>>>(wzW1, p_whi, p_wlo, HH*HH);
    tc_gemm_kernel<<<gg, 256>>>(p_ahi, p_alo, p_whi, p_wlo, p_wz,
                                bnz_g1, bnz_b1, bnz_m1, bnz_v1, HH, MTOT);
    scan_kernel<<<GRID_SCAN, 256, smem_scan>>>(p_wh, p_wz, uhW1, uzW1, out,
                                               p_hTh, p_hTl,
                                               p_fl + GRID_SCAN*FPAD);
}

// round 15
// speedup vs baseline: 1.1156x; 1.0309x over previous
#include <cuda_runtime.h>
#include <cuda_bf16.h>
#include <cstdint>
#include <math.h>

#define TT 1500
#define BB 16
#define DD 512
#define HH 1024
#define KEEPF 0.8f
#define EPSF 1e-5f
#define NTOT (TT*BB*HH)
#define GRID_SCAN 128
#define FPAD 32
#define MTOT (TT*BB)                 // 24000 rows
#define MTILES ((MTOT + 127)/128)    // 188
#define HSTR 1032                    // padded bf16 row stride (2064 B)

typedef unsigned long long u64;

#define CPA_COMMIT() asm volatile("cp.async.commit_group;" ::: "memory")
#define CPA_WAIT(n)  asm volatile("cp.async.wait_group %0;" :: "n"(n) : "memory")

#define SMEM_SWZ(o) ((o) ^ (((o) >> 3) & 0x70))

__device__ __forceinline__ uint32_t smem_u32(const void* p) {
    uint32_t a;
    asm("{ .reg .u64 t; cvta.to.shared.u64 t, %1; cvt.u32.u64 %0, t; }" : "=r"(a) : "l"(p));
    return a;
}

// warp-level bf16 tensor ops (baseline ISA — valid on compute_103 target)
#define LDSM_X4(r0,r1,r2,r3,addr) \
    asm volatile("ldmatrix.sync.aligned.m8n8.x4.shared.b16 {%0,%1,%2,%3}, [%4];" \
        : "=r"(r0), "=r"(r1), "=r"(r2), "=r"(r3) : "r"(addr))
#define LDSM_X2(r0,r1,addr) \
    asm volatile("ldmatrix.sync.aligned.m8n8.x2.shared.b16 {%0,%1}, [%2];" \
        : "=r"(r0), "=r"(r1) : "r"(addr))
#define MMA16816(d,a,b) \
    asm volatile("mma.sync.aligned.m16n8k16.row.col.f32.bf16.bf16.f32 " \
        "{%0,%1,%2,%3}, {%4,%5,%6,%7}, {%8,%9}, {%0,%1,%2,%3};" \
        : "+f"((d)[0]), "+f"((d)[1]), "+f"((d)[2]), "+f"((d)[3]) \
        : "r"((a)[0]), "r"((a)[1]), "r"((a)[2]), "r"((a)[3]), \
          "r"((b)[0]), "r"((b)[1]))

// -------- scratch (device globals: no allocation allowed) --------
__device__ float g_wh[NTOT];
__device__ float g_wz[NTOT];
__device__ float g_h0[NTOT];
__device__ __nv_bfloat16 g_hTh[BB*HH];   // h broadcast, bf16 hi
__device__ __nv_bfloat16 g_hTl[BB*HH];   // h broadcast, bf16 lo
__device__ int   g_flags[2*GRID_SCAN*FPAD];
__device__ __nv_bfloat16 g_ahi[MTOT*HH];
__device__ __nv_bfloat16 g_alo[MTOT*HH];
__device__ __nv_bfloat16 g_whi[HH*HH];
__device__ __nv_bfloat16 g_wlo[HH*HH];

// =================================================================
__global__ void init_kernel(const int* __restrict__ x_len,
                            float* __restrict__ out, int out_size)
{
    int i = blockIdx.x * blockDim.x + threadIdx.x;
    if (i < 2*GRID_SCAN*FPAD) g_flags[i] = 0;
    if (out_size >= NTOT + BB && i < BB) out[NTOT + i] = (float)x_len[i];
}

// =================================================================
// fp32 -> (bf16 hi, bf16 lo) split, vectorized
// =================================================================
__global__ void split_kernel(const float* __restrict__ src,
                             __nv_bfloat16* __restrict__ hi,
                             __nv_bfloat16* __restrict__ lo, int n)
{
    int i = (blockIdx.x * blockDim.x + threadIdx.x) * 4;
    int stride = gridDim.x * blockDim.x * 4;
    for (; i < n; i += stride) {
        float4 x = *(const float4*)(src + i);
        __nv_bfloat16 h0 = __float2bfloat16(x.x), h1 = __float2bfloat16(x.y);
        __nv_bfloat16 h2 = __float2bfloat16(x.z), h3 = __float2bfloat16(x.w);
        __nv_bfloat162 H0; H0.x = h0; H0.y = h1;
        __nv_bfloat162 H1; H1.x = h2; H1.y = h3;
        *(__nv_bfloat162*)(hi + i)     = H0;
        *(__nv_bfloat162*)(hi + i + 2) = H1;
        __nv_bfloat162 L0, L1;
        L0.x = __float2bfloat16(x.x - __bfloat162float(h0));
        L0.y = __float2bfloat16(x.y - __bfloat162float(h1));
        L1.x = __float2bfloat16(x.z - __bfloat162float(h2));
        L1.y = __float2bfloat16(x.w - __bfloat162float(h3));
        *(__nv_bfloat162*)(lo + i)     = L0;
        *(__nv_bfloat162*)(lo + i + 2) = L1;
    }
}

// =================================================================
// split-bf16 tensor GEMM + fused eval BN — DOUBLE-BUFFERED slabs.
// Flattened slab stream q = pass*nslab + ks over 3 passes
// (Ahi·Whi, Ahi·Wlo, Alo·Whi); stage slab q+1 while computing q.
// Dynamic smem: As[2] | Bs[2] | sc | sh.
// =================================================================
__global__ void __launch_bounds__(256) tc_gemm_kernel(
    const __nv_bfloat16* __restrict__ Ahi, const __nv_bfloat16* __restrict__ Alo,
    const __nv_bfloat16* __restrict__ Whi, const __nv_bfloat16* __restrict__ Wlo,
    float* __restrict__ C,
    const float* __restrict__ gam, const float* __restrict__ bet,
    const float* __restrict__ mu,  const float* __restrict__ var,
    int K, int Mtot)
{
    extern __shared__ unsigned char gsm[];
    uint32_t a_s = smem_u32(gsm);                 // As: 2 x 16 KB
    uint32_t b_s = a_s + 32768;                   // Bs: 2 x 16 KB
    float* s_sc = (float*)(gsm + 65536);
    float* s_sh = (float*)(gsm + 65536 + 512);

    int tid  = threadIdx.x;
    int w    = tid >> 5, lane = tid & 31;
    int wm   = w & 1;
    int wn   = w >> 1;
    int m0   = blockIdx.y * 128;
    int n0   = blockIdx.x * 128;

    if (tid < 128) {
        int n = n0 + tid;
        float inv = rsqrtf(var[n] + EPSF);
        float sc = gam[n] * inv;
        s_sc[tid] = sc;
        s_sh[tid] = bet[n] - mu[n] * sc;
    }

    float acc[4][4][4];
    #pragma unroll
    for (int i = 0; i < 4; i++)
        #pragma unroll
        for (int j = 0; j < 4; j++)
            #pragma unroll
            for (int q = 0; q < 4; q++) acc[i][j][q] = 0.f;

    uint32_t a_off0 = (uint32_t)((wm*64 + (lane & 15)) << 7) + ((lane >> 4) << 4);
    uint32_t b_off0 = (uint32_t)((wn*32 + (lane & 7)) << 7) + (((lane >> 3) & 1) << 4);

    int nslab = K >> 6;
    int total = 3 * nslab;
    const __nv_bfloat16* APs[3] = {Ahi, Ahi, Alo};
    const __nv_bfloat16* BPs[3] = {Whi, Wlo, Whi};

    #define GEMM_STAGE(q_, buf_) { \
        int pass_ = (q_) / nslab, ks_ = (q_) % nslab; \
        const __nv_bfloat16* Ap_ = APs[pass_]; \
        const __nv_bfloat16* Bp_ = BPs[pass_]; \
        uint32_t ab_ = a_s + (buf_)*16384, bb_ = b_s + (buf_)*16384; \
        _Pragma("unroll") \
        for (int i_ = 0; i_ < 4; i_++) { \
            int idx_ = tid + (i_ << 8); \
            int r_ = idx_ >> 3, g_ = idx_ & 7; \
            uint32_t dsw_ = SMEM_SWZ((uint32_t)((r_ << 7) + (g_ << 4))); \
            int arow_ = m0 + r_; \
            int sz_ = (arow_ < Mtot) ? 16 : 0; \
            if (arow_ >= Mtot) arow_ = Mtot - 1; \
            const __nv_bfloat16* sa_ = Ap_ + (size_t)arow_*K + (ks_ << 6) + (g_ << 3); \
            asm volatile("cp.async.cg.shared.global [%0], [%1], 16, %2;" \
                         :: "r"(ab_ + dsw_), "l"(sa_), "r"(sz_) : "memory"); \
            const __nv_bfloat16* sb_ = Bp_ + (size_t)(n0 + r_)*K + (ks_ << 6) + (g_ << 3); \
            asm volatile("cp.async.cg.shared.global [%0], [%1], 16;" \
                         :: "r"(bb_ + dsw_), "l"(sb_) : "memory"); \
        } \
        CPA_COMMIT(); }

    GEMM_STAGE(0, 0);
    for (int q = 0; q < total; q++) {
        int p = q & 1;
        if (q + 1 < total) {
            GEMM_STAGE(q + 1, 1 - p);
            CPA_WAIT(1);
        } else {
            CPA_WAIT(0);
        }
        __syncthreads();

        uint32_t ab = a_s + p*16384, bb = b_s + p*16384;
        #pragma unroll
        for (int kst = 0; kst < 4; kst++) {
            uint32_t af[4][4], bf[4][2];
            #pragma unroll
            for (int i = 0; i < 4; i++) {
                uint32_t off = a_off0 + (uint32_t)(i << 11) + (uint32_t)(kst << 5);
                LDSM_X4(af[i][0], af[i][1], af[i][2], af[i][3], ab + SMEM_SWZ(off));
            }
            #pragma unroll
            for (int j = 0; j < 4; j++) {
                uint32_t off = b_off0 + (uint32_t)(j << 10) + (uint32_t)(kst << 5);
                LDSM_X2(bf[j][0], bf[j][1], bb + SMEM_SWZ(off));
            }
            #pragma unroll
            for (int i = 0; i < 4; i++)
                #pragma unroll
                for (int j = 0; j < 4; j++)
                    MMA16816(acc[i][j], af[i], bf[j]);
        }
        __syncthreads();   // buf p safe to overwrite next iteration
    }
    #undef GEMM_STAGE

    #pragma unroll
    for (int i = 0; i < 4; i++) {
        int r0 = m0 + wm*64 + i*16 + (lane >> 2);
        #pragma unroll
        for (int j = 0; j < 4; j++) {
            int c = wn*32 + j*8 + 2*(lane & 3);
            float sc0 = s_sc[c], sc1 = s_sc[c+1];
            float sh0 = s_sh[c], sh1 = s_sh[c+1];
            if (r0 < Mtot) {
                float2 v;
                v.x = acc[i][j][0] * sc0 + sh0;
                v.y = acc[i][j][1] * sc1 + sh1;
                *(float2*)(C + (size_t)r0*HH + n0 + c) = v;
            }
            if (r0 + 8 < Mtot) {
                float2 v;
                v.x = acc[i][j][2] * sc0 + sh0;
                v.y = acc[i][j][3] * sc1 + sh1;
                *(float2*)(C + (size_t)(r0+8)*HH + n0 + c) = v;
            }
        }
    }
}

// =================================================================
// persistent liGRU scan v9 = R14 + gate/poll overlap.
// After partial-write sync: threads <64 gate + named-barrier +
// tid0 flag release; threads >=128 concurrently poll all 128
// producer flags.  Release never depends on polling (no deadlock).
// =================================================================
__global__ void __launch_bounds__(256, 1) scan_kernel(
    const float* __restrict__ WH, const float* __restrict__ WZ,
    const float* __restrict__ Uh, const float* __restrict__ Uz,
    float* __restrict__ Hout,
    __nv_bfloat16* __restrict__ hTh, __nv_bfloat16* __restrict__ hTl,
    int* __restrict__ flags)
{
    extern __shared__ unsigned char smem_raw[];
    __nv_bfloat16* h_hi = (__nv_bfloat16*)smem_raw;        // [16][HSTR]
    __nv_bfloat16* h_lo = h_hi + 16*HSTR;                  // [16][HSTR]
    float* red2 = (float*)(h_lo + 16*HSTR);                // [8][128]
    uint32_t hi_s = smem_u32(h_hi), lo_s = smem_u32(h_lo);

    int tid = threadIdx.x, w = tid >> 5, lane = tid & 31;
    int g = w >> 2;            // 0 = z-gate, 1 = a-gate
    int s = w & 3;             // k-slice within each chunk (128 wide)
    int j0 = blockIdx.x * 8;

    // ---- stage U as bf16 hi/lo into smem (reusing h buffers) ----
    for (int idx = tid; idx < 8*HH; idx += 256) {
        int r = idx >> 10, k = idx & (HH-1);
        float vz = Uz[(size_t)(j0+r)*HH + k];
        float vh = Uh[(size_t)(j0+r)*HH + k];
        __nv_bfloat16 zh = __float2bfloat16(vz);
        __nv_bfloat16 hh = __float2bfloat16(vh);
        h_hi[r*HSTR + k]     = zh;
        h_hi[(r+8)*HSTR + k] = __float2bfloat16(vz - __bfloat162float(zh));
        h_lo[r*HSTR + k]     = hh;
        h_lo[(r+8)*HSTR + k] = __float2bfloat16(vh - __bfloat162float(hh));
    }
    __syncthreads();

    // ---- register-stationary U B-frags ----
    uint32_t ufh[16][2], ufl[16][2];
    {
        uint32_t base = g ? lo_s : hi_s;
        uint32_t rowoff = (uint32_t)((lane & 7)*2064) + (uint32_t)(((lane >> 3) & 1)*16);
        #pragma unroll
        for (int kk = 0; kk < 16; kk++) {
            int kglob = ((kk < 8) ? 0 : 512) + s*128 + (kk & 7)*16;
            uint32_t kb = (uint32_t)(kglob*2);
            LDSM_X2(ufh[kk][0], ufh[kk][1], base + rowoff + kb);
            LDSM_X2(ufl[kk][0], ufl[kk][1], base + 8*2064 + rowoff + kb);
        }
    }
    __syncthreads();

    // ---- zero h smem (h_{-1} = 0) ----
    {
        uint4 z4; z4.x = z4.y = z4.z = z4.w = 0u;
        for (int idx = tid; idx < (2*16*HSTR*2)/16; idx += 256)
            ((uint4*)smem_raw)[idx] = z4;
    }
    __syncthreads();

    // A-frag lane address (h tile: rows = batch, k-contiguous)
    uint32_t a_off = (uint32_t)((lane & 15)*2064) + (uint32_t)((lane >> 4)*16);

    // gate thread mapping
    int b_o = tid & 15, jp = tid >> 4;
    int lr  = ((b_o & 7)*4 + jp)*4 + ((b_o >> 3) ? 2 : 0);
    bool is_gate = (tid < 64);
    int jg = j0 + 2*jp;
    float hold0 = 0.f, hold1 = 0.f;

    for (int t = 0; t < TT; t++) {
        float2 wz2 = make_float2(0.f, 0.f), wh2 = wz2;
        size_t ob = 0;
        if (is_gate) {
            ob = ((size_t)t*BB + b_o)*HH + jg;
            wz2 = *(const float2*)(WZ + ob);
            wh2 = *(const float2*)(WH + ob);
        }

        float acc0[4] = {0.f,0.f,0.f,0.f};
        float acc1[4] = {0.f,0.f,0.f,0.f};
        float acc2[4] = {0.f,0.f,0.f,0.f};

        // ---- phase 0: chunk0 resident, ksteps 0..7 (all warps) ----
        CPA_WAIT(1);
        __syncthreads();
        #pragma unroll
        for (int kk = 0; kk < 8; kk++) {
            uint32_t kb = (uint32_t)((s*128 + kk*16)*2);
            uint32_t ah[4], al[4];
            LDSM_X4(ah[0], ah[1], ah[2], ah[3], hi_s + a_off + kb);
            LDSM_X4(al[0], al[1], al[2], al[3], lo_s + a_off + kb);
            MMA16816(acc0, ah, ufh[kk]);
            MMA16816(acc1, ah, ufl[kk]);
            MMA16816(acc2, al, ufh[kk]);
        }
        // ---- phase 1: chunk1 resident, ksteps 8..15 ----
        CPA_WAIT(0);
        __syncthreads();
        #pragma unroll
        for (int kk = 8; kk < 16; kk++) {
            uint32_t kb = (uint32_t)((512 + s*128 + (kk-8)*16)*2);
            uint32_t ah[4], al[4];
            LDSM_X4(ah[0], ah[1], ah[2], ah[3], hi_s + a_off + kb);
            LDSM_X4(al[0], al[1], al[2], al[3], lo_s + a_off + kb);
            MMA16816(acc0, ah, ufh[kk]);
            MMA16816(acc1, ah, ufl[kk]);
            MMA16816(acc2, al, ufh[kk]);
        }
        #pragma unroll
        for (int q = 0; q < 4; q++) acc0[q] += acc1[q] + acc2[q];

        // ---- partial write: red2[w][lane*4..+3] ----
        *(float4*)(red2 + w*128 + lane*4) = *(float4*)acc0;
        __syncthreads();

        // ---- OVERLAPPED: gate (tid<64) + release || poll (tid>=128) ----
        if (is_gate) {
            const float* rz = red2 + lr;           // z-gate: warps 0-3
            const float* ra = red2 + 4*128 + lr;   // a-gate: warps 4-7
            float z0 = 0.f, z1 = 0.f, a0 = 0.f, a1 = 0.f;
            #pragma unroll
            for (int ss = 0; ss < 4; ss++) {
                float2 vz = *(const float2*)(rz + ss*128);
                float2 va = *(const float2*)(ra + ss*128);
                z0 += vz.x; z1 += vz.y;
                a0 += va.x; a1 += va.y;
            }
            float zt0 = 1.f / (1.f + __expf(-(wz2.x + z0)));
            float zt1 = 1.f / (1.f + __expf(-(wz2.y + z1)));
            float hc0 = fmaxf(wh2.x + a0, 0.f) * KEEPF;
            float hc1 = fmaxf(wh2.y + a1, 0.f) * KEEPF;
            float hn0 = zt0*hold0 + (1.f - zt0)*hc0;
            float hn1 = zt1*hold1 + (1.f - zt1)*hc1;
            hold0 = hn0; hold1 = hn1;
            float2 o; o.x = hn0; o.y = hn1;
            *(float2*)(Hout + ob) = o;
            __nv_bfloat162 hi2, lo2;
            hi2.x = __float2bfloat16(hn0);
            hi2.y = __float2bfloat16(hn1);
            lo2.x = __float2bfloat16(hn0 - __bfloat162float(hi2.x));
            lo2.y = __float2bfloat16(hn1 - __bfloat162float(hi2.y));
            *(__nv_bfloat162*)(hTh + b_o*HH + jg) = hi2;
            *(__nv_bfloat162*)(hTl + b_o*HH + jg) = lo2;
            // all 64 gate threads' hT writes done -> release our flag
            asm volatile("bar.sync 1, 64;" ::: "memory");
            if (tid == 0) {
                asm volatile("st.release.gpu.global.s32 [%0], %1;"
                             :: "l"(flags + blockIdx.x*FPAD), "r"(t+1) : "memory");
            }
        } else if (tid >= 128 && t < TT-1) {
            // poll producer flags concurrently with our gate
            const int* fp = flags + (tid - 128)*FPAD;
            int v;
            do {
                asm volatile("ld.acquire.gpu.global.s32 %0, [%1];"
                             : "=r"(v) : "l"(fp) : "memory");
            } while (v <= t);
        }
        __syncthreads();
        if (t == TT-1) break;

        // ---- issue pipelined h reload: 2 k-chunks x (hi + lo) ----
        #pragma unroll
        for (int i = 0; i < 4; i++) {
            int idx = tid + (i << 8);              // 0..1023
            int b = idx >> 6, kq = idx & 63;       // 16B granule (8 bf16)
            uint32_t dofs = (uint32_t)(b*2064 + kq*16);
            const __nv_bfloat16* s0p = hTh + b*HH + kq*8;
            const __nv_bfloat16* s1p = hTl + b*HH + kq*8;
            asm volatile("cp.async.cg.shared.global [%0], [%1], 16;"
                         :: "r"(hi_s + dofs), "l"(s0p) : "memory");
            asm volatile("cp.async.cg.shared.global [%0], [%1], 16;"
                         :: "r"(lo_s + dofs), "l"(s1p) : "memory");
        }
        CPA_COMMIT();
        #pragma unroll
        for (int i = 0; i < 4; i++) {
            int idx = tid + (i << 8);
            int b = idx >> 6, kq = (idx & 63) + 64;
            uint32_t dofs = (uint32_t)(b*2064 + kq*16);
            const __nv_bfloat16* s0p = hTh + b*HH + kq*8;
            const __nv_bfloat16* s1p = hTl + b*HH + kq*8;
            asm volatile("cp.async.cg.shared.global [%0], [%1], 16;"
                         :: "r"(hi_s + dofs), "l"(s0p) : "memory");
            asm volatile("cp.async.cg.shared.global [%0], [%1], 16;"
                         :: "r"(lo_s + dofs), "l"(s1p) : "memory");
        }
        CPA_COMMIT();
    }
}

// =================================================================
extern "C" void kernel_launch(void* const* d_in, const int* in_sizes, int n_in,
                              void* d_out, int out_size)
{
    const float* x     = (const float*)d_in[0];
    const int*   x_len = (const int*)  d_in[1];
    const float* whW0  = (const float*)d_in[2];
    const float* wzW0  = (const float*)d_in[3];
    const float* uhW0  = (const float*)d_in[4];
    const float* uzW0  = (const float*)d_in[5];
    const float* bnh_g0 = (const float*)d_in[6];
    const float* bnh_b0 = (const float*)d_in[7];
    const float* bnh_m0 = (const float*)d_in[8];
    const float* bnh_v0 = (const float*)d_in[9];
    const float* bnz_g0 = (const float*)d_in[10];
    const float* bnz_b0 = (const float*)d_in[11];
    const float* bnz_m0 = (const float*)d_in[12];
    const float* bnz_v0 = (const float*)d_in[13];
    const float* whW1  = (const float*)d_in[14];
    const float* wzW1  = (const float*)d_in[15];
    const float* uhW1  = (const float*)d_in[16];
    const float* uzW1  = (const float*)d_in[17];
    const float* bnh_g1 = (const float*)d_in[18];
    const float* bnh_b1 = (const float*)d_in[19];
    const float* bnh_m1 = (const float*)d_in[20];
    const float* bnh_v1 = (const float*)d_in[21];
    const float* bnz_g1 = (const float*)d_in[22];
    const float* bnz_b1 = (const float*)d_in[23];
    const float* bnz_m1 = (const float*)d_in[24];
    const float* bnz_v1 = (const float*)d_in[25];

    float* out = (float*)d_out;

    float *p_wh, *p_wz, *p_h0; int* p_fl;
    __nv_bfloat16 *p_ahi, *p_alo, *p_whi, *p_wlo, *p_hTh, *p_hTl;
    cudaGetSymbolAddress((void**)&p_wh, g_wh);
    cudaGetSymbolAddress((void**)&p_wz, g_wz);
    cudaGetSymbolAddress((void**)&p_h0, g_h0);
    cudaGetSymbolAddress((void**)&p_fl, g_flags);
    cudaGetSymbolAddress((void**)&p_ahi, g_ahi);
    cudaGetSymbolAddress((void**)&p_alo, g_alo);
    cudaGetSymbolAddress((void**)&p_whi, g_whi);
    cudaGetSymbolAddress((void**)&p_wlo, g_wlo);
    cudaGetSymbolAddress((void**)&p_hTh, g_hTh);
    cudaGetSymbolAddress((void**)&p_hTl, g_hTl);

    int smem_scan = 2*16*HSTR*2 + 8*128*4;   // 66048 + 4096 = 70144 B
    cudaFuncSetAttribute(scan_kernel,
        cudaFuncAttributeMaxDynamicSharedMemorySize, smem_scan);

    int smem_gemm = 65536 + 1024;            // 2x(As+Bs) + sc/sh
    cudaFuncSetAttribute(tc_gemm_kernel,
        cudaFuncAttributeMaxDynamicSharedMemorySize, smem_gemm);

    init_kernel<<<32, 256>>>(x_len, out, out_size);

    dim3 gg(HH/128, MTILES);     // (8, 188)

    // ---- layer 0 (K = 512) ----
    split_kernel<<<592, 256>>>(x, p_ahi, p_alo, MTOT*DD);
    split_kernel<<<592, 256>>>(whW0, p_whi, p_wlo, HH*DD);
    tc_gemm_kernel<<<gg, 256, smem_gemm>>>(p_ahi, p_alo, p_whi, p_wlo, p_wh,
                                bnh_g0, bnh_b0, bnh_m0, bnh_v0, DD, MTOT);
    split_kernel<<<592, 256>>>(wzW0, p_whi, p_wlo, HH*DD);
    tc_gemm_kernel<<<gg, 256, smem_gemm>>>(p_ahi, p_alo, p_whi, p_wlo, p_wz,
                                bnz_g0, bnz_b0, bnz_m0, bnz_v0, DD, MTOT);
    scan_kernel<<<GRID_SCAN, 256, smem_scan>>>(p_wh, p_wz, uhW0, uzW0, p_h0,
                                               p_hTh, p_hTl, p_fl);

    // ---- layer 1 (K = 1024) ----
    split_kernel<<<592, 256>>>(p_h0, p_ahi, p_alo, MTOT*HH);
    split_kernel<<<592, 256>>>(whW1, p_whi, p_wlo, HH*HH);
    tc_gemm_kernel<<<gg, 256, smem_gemm>>>(p_ahi, p_alo, p_whi, p_wlo, p_wh,
                                bnh_g1, bnh_b1, bnh_m1, bnh_v1, HH, MTOT);
    split_kernel<<<592, 256>>>(wzW1, p_whi, p_wlo, HH*HH);
    tc_gemm_kernel<<<gg, 256, smem_gemm>>>(p_ahi, p_alo, p_whi, p_wlo, p_wz,
                                bnz_g1, bnz_b1, bnz_m1, bnz_v1, HH, MTOT);
    scan_kernel<<<GRID_SCAN, 256, smem_scan>>>(p_wh, p_wz, uhW1, uzW1, out,
                                               p_hTh, p_hTl,
                                               p_fl + GRID_SCAN*FPAD);
}

// round 16
// speedup vs baseline: 1.2316x; 1.1039x over previous
#include <cuda_runtime.h>
#include <cuda_bf16.h>
#include <cstdint>
#include <math.h>

#define TT 1500
#define BB 16
#define DD 512
#define HH 1024
#define KEEPF 0.8f
#define EPSF 1e-5f
#define NTOT (TT*BB*HH)
#define GRID_SCAN 128
#define FPAD 32
#define MTOT (TT*BB)                 // 24000 rows
#define MTILES ((MTOT + 127)/128)    // 188
#define HSTR 1032                    // padded bf16 row stride (2064 B)

typedef unsigned long long u64;

#define CPA_COMMIT() asm volatile("cp.async.commit_group;" ::: "memory")
#define CPA_WAIT(n)  asm volatile("cp.async.wait_group %0;" :: "n"(n) : "memory")

#define SMEM_SWZ(o) ((o) ^ (((o) >> 3) & 0x70))

__device__ __forceinline__ uint32_t smem_u32(const void* p) {
    uint32_t a;
    asm("{ .reg .u64 t; cvta.to.shared.u64 t, %1; cvt.u32.u64 %0, t; }" : "=r"(a) : "l"(p));
    return a;
}

// warp-level bf16 tensor ops (baseline ISA — valid on compute_103 target)
#define LDSM_X4(r0,r1,r2,r3,addr) \
    asm volatile("ldmatrix.sync.aligned.m8n8.x4.shared.b16 {%0,%1,%2,%3}, [%4];" \
        : "=r"(r0), "=r"(r1), "=r"(r2), "=r"(r3) : "r"(addr))
#define LDSM_X2(r0,r1,addr) \
    asm volatile("ldmatrix.sync.aligned.m8n8.x2.shared.b16 {%0,%1}, [%2];" \
        : "=r"(r0), "=r"(r1) : "r"(addr))
#define MMA16816(d,a,b) \
    asm volatile("mma.sync.aligned.m16n8k16.row.col.f32.bf16.bf16.f32 " \
        "{%0,%1,%2,%3}, {%4,%5,%6,%7}, {%8,%9}, {%0,%1,%2,%3};" \
        : "+f"((d)[0]), "+f"((d)[1]), "+f"((d)[2]), "+f"((d)[3]) \
        : "r"((a)[0]), "r"((a)[1]), "r"((a)[2]), "r"((a)[3]), \
          "r"((b)[0]), "r"((b)[1]))

// -------- scratch (device globals: no allocation allowed) --------
__device__ float g_wh[NTOT];
__device__ float g_wz[NTOT];
__device__ float g_h0[NTOT];
__device__ __nv_bfloat16 g_hTh[BB*HH];   // h broadcast, bf16 hi
__device__ __nv_bfloat16 g_hTl[BB*HH];   // h broadcast, bf16 lo
__device__ int   g_flags[2*FPAD];        // one step counter per layer
__device__ __nv_bfloat16 g_ahi[MTOT*HH];
__device__ __nv_bfloat16 g_alo[MTOT*HH];
__device__ __nv_bfloat16 g_whi[HH*HH];
__device__ __nv_bfloat16 g_wlo[HH*HH];

// =================================================================
__global__ void init_kernel(const int* __restrict__ x_len,
                            float* __restrict__ out, int out_size)
{
    int i = blockIdx.x * blockDim.x + threadIdx.x;
    if (i < 2*FPAD) g_flags[i] = 0;
    if (out_size >= NTOT + BB && i < BB) out[NTOT + i] = (float)x_len[i];
}

// =================================================================
// fp32 -> (bf16 hi, bf16 lo) split, vectorized
// =================================================================
__global__ void split_kernel(const float* __restrict__ src,
                             __nv_bfloat16* __restrict__ hi,
                             __nv_bfloat16* __restrict__ lo, int n)
{
    int i = (blockIdx.x * blockDim.x + threadIdx.x) * 4;
    int stride = gridDim.x * blockDim.x * 4;
    for (; i < n; i += stride) {
        float4 x = *(const float4*)(src + i);
        __nv_bfloat16 h0 = __float2bfloat16(x.x), h1 = __float2bfloat16(x.y);
        __nv_bfloat16 h2 = __float2bfloat16(x.z), h3 = __float2bfloat16(x.w);
        __nv_bfloat162 H0; H0.x = h0; H0.y = h1;
        __nv_bfloat162 H1; H1.x = h2; H1.y = h3;
        *(__nv_bfloat162*)(hi + i)     = H0;
        *(__nv_bfloat162*)(hi + i + 2) = H1;
        __nv_bfloat162 L0, L1;
        L0.x = __float2bfloat16(x.x - __bfloat162float(h0));
        L0.y = __float2bfloat16(x.y - __bfloat162float(h1));
        L1.x = __float2bfloat16(x.z - __bfloat162float(h2));
        L1.y = __float2bfloat16(x.w - __bfloat162float(h3));
        *(__nv_bfloat162*)(lo + i)     = L0;
        *(__nv_bfloat162*)(lo + i + 2) = L1;
    }
}

// =================================================================
// split-bf16 tensor GEMM + fused eval BN — double-buffered (R15).
// =================================================================
__global__ void __launch_bounds__(256) tc_gemm_kernel(
    const __nv_bfloat16* __restrict__ Ahi, const __nv_bfloat16* __restrict__ Alo,
    const __nv_bfloat16* __restrict__ Whi, const __nv_bfloat16* __restrict__ Wlo,
    float* __restrict__ C,
    const float* __restrict__ gam, const float* __restrict__ bet,
    const float* __restrict__ mu,  const float* __restrict__ var,
    int K, int Mtot)
{
    extern __shared__ unsigned char gsm[];
    uint32_t a_s = smem_u32(gsm);                 // As: 2 x 16 KB
    uint32_t b_s = a_s + 32768;                   // Bs: 2 x 16 KB
    float* s_sc = (float*)(gsm + 65536);
    float* s_sh = (float*)(gsm + 65536 + 512);

    int tid  = threadIdx.x;
    int w    = tid >> 5, lane = tid & 31;
    int wm   = w & 1;
    int wn   = w >> 1;
    int m0   = blockIdx.y * 128;
    int n0   = blockIdx.x * 128;

    if (tid < 128) {
        int n = n0 + tid;
        float inv = rsqrtf(var[n] + EPSF);
        float sc = gam[n] * inv;
        s_sc[tid] = sc;
        s_sh[tid] = bet[n] - mu[n] * sc;
    }

    float acc[4][4][4];
    #pragma unroll
    for (int i = 0; i < 4; i++)
        #pragma unroll
        for (int j = 0; j < 4; j++)
            #pragma unroll
            for (int q = 0; q < 4; q++) acc[i][j][q] = 0.f;

    uint32_t a_off0 = (uint32_t)((wm*64 + (lane & 15)) << 7) + ((lane >> 4) << 4);
    uint32_t b_off0 = (uint32_t)((wn*32 + (lane & 7)) << 7) + (((lane >> 3) & 1) << 4);

    int nslab = K >> 6;
    int total = 3 * nslab;
    const __nv_bfloat16* APs[3] = {Ahi, Ahi, Alo};
    const __nv_bfloat16* BPs[3] = {Whi, Wlo, Whi};

    #define GEMM_STAGE(q_, buf_) { \
        int pass_ = (q_) / nslab, ks_ = (q_) % nslab; \
        const __nv_bfloat16* Ap_ = APs[pass_]; \
        const __nv_bfloat16* Bp_ = BPs[pass_]; \
        uint32_t ab_ = a_s + (buf_)*16384, bb_ = b_s + (buf_)*16384; \
        _Pragma("unroll") \
        for (int i_ = 0; i_ < 4; i_++) { \
            int idx_ = tid + (i_ << 8); \
            int r_ = idx_ >> 3, g_ = idx_ & 7; \
            uint32_t dsw_ = SMEM_SWZ((uint32_t)((r_ << 7) + (g_ << 4))); \
            int arow_ = m0 + r_; \
            int sz_ = (arow_ < Mtot) ? 16 : 0; \
            if (arow_ >= Mtot) arow_ = Mtot - 1; \
            const __nv_bfloat16* sa_ = Ap_ + (size_t)arow_*K + (ks_ << 6) + (g_ << 3); \
            asm volatile("cp.async.cg.shared.global [%0], [%1], 16, %2;" \
                         :: "r"(ab_ + dsw_), "l"(sa_), "r"(sz_) : "memory"); \
            const __nv_bfloat16* sb_ = Bp_ + (size_t)(n0 + r_)*K + (ks_ << 6) + (g_ << 3); \
            asm volatile("cp.async.cg.shared.global [%0], [%1], 16;" \
                         :: "r"(bb_ + dsw_), "l"(sb_) : "memory"); \
        } \
        CPA_COMMIT(); }

    GEMM_STAGE(0, 0);
    for (int q = 0; q < total; q++) {
        int p = q & 1;
        if (q + 1 < total) {
            GEMM_STAGE(q + 1, 1 - p);
            CPA_WAIT(1);
        } else {
            CPA_WAIT(0);
        }
        __syncthreads();

        uint32_t ab = a_s + p*16384, bb = b_s + p*16384;
        #pragma unroll
        for (int kst = 0; kst < 4; kst++) {
            uint32_t af[4][4], bf[4][2];
            #pragma unroll
            for (int i = 0; i < 4; i++) {
                uint32_t off = a_off0 + (uint32_t)(i << 11) + (uint32_t)(kst << 5);
                LDSM_X4(af[i][0], af[i][1], af[i][2], af[i][3], ab + SMEM_SWZ(off));
            }
            #pragma unroll
            for (int j = 0; j < 4; j++) {
                uint32_t off = b_off0 + (uint32_t)(j << 10) + (uint32_t)(kst << 5);
                LDSM_X2(bf[j][0], bf[j][1], bb + SMEM_SWZ(off));
            }
            #pragma unroll
            for (int i = 0; i < 4; i++)
                #pragma unroll
                for (int j = 0; j < 4; j++)
                    MMA16816(acc[i][j], af[i], bf[j]);
        }
        __syncthreads();   // buf p safe to overwrite next iteration
    }
    #undef GEMM_STAGE

    #pragma unroll
    for (int i = 0; i < 4; i++) {
        int r0 = m0 + wm*64 + i*16 + (lane >> 2);
        #pragma unroll
        for (int j = 0; j < 4; j++) {
            int c = wn*32 + j*8 + 2*(lane & 3);
            float sc0 = s_sc[c], sc1 = s_sc[c+1];
            float sh0 = s_sh[c], sh1 = s_sh[c+1];
            if (r0 < Mtot) {
                float2 v;
                v.x = acc[i][j][0] * sc0 + sh0;
                v.y = acc[i][j][1] * sc1 + sh1;
                *(float2*)(C + (size_t)r0*HH + n0 + c) = v;
            }
            if (r0 + 8 < Mtot) {
                float2 v;
                v.x = acc[i][j][2] * sc0 + sh0;
                v.y = acc[i][j][3] * sc1 + sh1;
                *(float2*)(C + (size_t)(r0+8)*HH + n0 + c) = v;
            }
        }
    }
}

// =================================================================
// persistent liGRU scan v10: DUAL-GATE warps + counter barrier.
// Warp w computes BOTH z and a gates for k-slice
//   [64w, 64w+64) ∪ [512+64w, 512+64w+64)
// -> halved LDSM (h frags loaded once), 6 independent MMA chains.
// Barrier: producers red.release.add ONE counter; one thread polls
// one line for v >= (t+1)*GRID_SCAN.
// =================================================================
__global__ void __launch_bounds__(256, 1) scan_kernel(
    const float* __restrict__ WH, const float* __restrict__ WZ,
    const float* __restrict__ Uh, const float* __restrict__ Uz,
    float* __restrict__ Hout,
    __nv_bfloat16* __restrict__ hTh, __nv_bfloat16* __restrict__ hTl,
    int* __restrict__ ctr)
{
    extern __shared__ unsigned char smem_raw[];
    __nv_bfloat16* h_hi = (__nv_bfloat16*)smem_raw;        // [16][HSTR]
    __nv_bfloat16* h_lo = h_hi + 16*HSTR;                  // [16][HSTR]
    float* red2 = (float*)(h_lo + 16*HSTR);                // [8][2][128]
    uint32_t hi_s = smem_u32(h_hi), lo_s = smem_u32(h_lo);

    int tid = threadIdx.x, w = tid >> 5, lane = tid & 31;
    int j0 = blockIdx.x * 8;

    // ---- stage U as bf16 hi/lo into smem (reusing h buffers) ----
    // h_hi rows 0-7: Uz-hi, rows 8-15: Uz-lo
    // h_lo rows 0-7: Uh-hi, rows 8-15: Uh-lo
    for (int idx = tid; idx < 8*HH; idx += 256) {
        int r = idx >> 10, k = idx & (HH-1);
        float vz = Uz[(size_t)(j0+r)*HH + k];
        float vh = Uh[(size_t)(j0+r)*HH + k];
        __nv_bfloat16 zh = __float2bfloat16(vz);
        __nv_bfloat16 hh = __float2bfloat16(vh);
        h_hi[r*HSTR + k]     = zh;
        h_hi[(r+8)*HSTR + k] = __float2bfloat16(vz - __bfloat162float(zh));
        h_lo[r*HSTR + k]     = hh;
        h_lo[(r+8)*HSTR + k] = __float2bfloat16(vh - __bfloat162float(hh));
    }
    __syncthreads();

    // ---- register-stationary U B-frags, BOTH gates ----
    // k(kk) = (kk<4 ? 0 : 512) + 64*w + 16*(kk&3)
    uint32_t uzh[8][2], uzl[8][2], uhh[8][2], uhl[8][2];
    {
        uint32_t rowoff = (uint32_t)((lane & 7)*2064) + (uint32_t)(((lane >> 3) & 1)*16);
        #pragma unroll
        for (int kk = 0; kk < 8; kk++) {
            int kglob = ((kk < 4) ? 0 : 512) + 64*w + 16*(kk & 3);
            uint32_t kb = (uint32_t)(kglob*2);
            LDSM_X2(uzh[kk][0], uzh[kk][1], hi_s + rowoff + kb);
            LDSM_X2(uzl[kk][0], uzl[kk][1], hi_s + 8*2064 + rowoff + kb);
            LDSM_X2(uhh[kk][0], uhh[kk][1], lo_s + rowoff + kb);
            LDSM_X2(uhl[kk][0], uhl[kk][1], lo_s + 8*2064 + rowoff + kb);
        }
    }
    __syncthreads();

    // ---- zero h smem (h_{-1} = 0) ----
    {
        uint4 z4; z4.x = z4.y = z4.z = z4.w = 0u;
        for (int idx = tid; idx < (2*16*HSTR*2)/16; idx += 256)
            ((uint4*)smem_raw)[idx] = z4;
    }
    __syncthreads();

    // A-frag lane address (h tile: rows = batch, k-contiguous)
    uint32_t a_off = (uint32_t)((lane & 15)*2064) + (uint32_t)((lane >> 4)*16);

    // gate thread mapping (tid < 64): (b, col-pair jp)
    int b_o = tid & 15, jp = tid >> 4;
    int lr  = ((b_o & 7)*4 + jp)*4 + ((b_o >> 3) ? 2 : 0);
    bool is_gate = (tid < 64);
    int jg = j0 + 2*jp;
    float hold0 = 0.f, hold1 = 0.f;

    for (int t = 0; t < TT; t++) {
        float2 wz2 = make_float2(0.f, 0.f), wh2 = wz2;
        size_t ob = 0;
        if (is_gate) {
            ob = ((size_t)t*BB + b_o)*HH + jg;
            wz2 = *(const float2*)(WZ + ob);
            wh2 = *(const float2*)(WH + ob);
        }

        float az0[4] = {0,0,0,0}, az1[4] = {0,0,0,0}, az2[4] = {0,0,0,0};
        float au0[4] = {0,0,0,0}, au1[4] = {0,0,0,0}, au2[4] = {0,0,0,0};

        // ---- phase 0: chunk0 resident (k<512): ksteps 0..3 ----
        CPA_WAIT(1);
        __syncthreads();
        #pragma unroll
        for (int kk = 0; kk < 4; kk++) {
            uint32_t kb = (uint32_t)((64*w + 16*kk)*2);
            uint32_t ah[4], al[4];
            LDSM_X4(ah[0], ah[1], ah[2], ah[3], hi_s + a_off + kb);
            LDSM_X4(al[0], al[1], al[2], al[3], lo_s + a_off + kb);
            MMA16816(az0, ah, uzh[kk]);
            MMA16816(az1, ah, uzl[kk]);
            MMA16816(az2, al, uzh[kk]);
            MMA16816(au0, ah, uhh[kk]);
            MMA16816(au1, ah, uhl[kk]);
            MMA16816(au2, al, uhh[kk]);
        }
        // ---- phase 1: chunk1 resident (k>=512): ksteps 4..7 ----
        CPA_WAIT(0);
        __syncthreads();
        #pragma unroll
        for (int kk = 4; kk < 8; kk++) {
            uint32_t kb = (uint32_t)((512 + 64*w + 16*(kk-4))*2);
            uint32_t ah[4], al[4];
            LDSM_X4(ah[0], ah[1], ah[2], ah[3], hi_s + a_off + kb);
            LDSM_X4(al[0], al[1], al[2], al[3], lo_s + a_off + kb);
            MMA16816(az0, ah, uzh[kk]);
            MMA16816(az1, ah, uzl[kk]);
            MMA16816(az2, al, uzh[kk]);
            MMA16816(au0, ah, uhh[kk]);
            MMA16816(au1, ah, uhl[kk]);
            MMA16816(au2, al, uhh[kk]);
        }
        #pragma unroll
        for (int q = 0; q < 4; q++) {
            az0[q] += az1[q] + az2[q];
            au0[q] += au1[q] + au2[q];
        }

        // ---- partial write: red2[w][gate][lane*4..+3] ----
        *(float4*)(red2 + (w*2    )*128 + lane*4) = *(float4*)az0;
        *(float4*)(red2 + (w*2 + 1)*128 + lane*4) = *(float4*)au0;
        __syncthreads();

        // ---- OVERLAPPED: gate+release (tid<64) || poll (tid==128) ----
        if (is_gate) {
            float z0 = 0.f, z1 = 0.f, a0 = 0.f, a1 = 0.f;
            #pragma unroll
            for (int ss = 0; ss < 8; ss++) {
                float2 vz = *(const float2*)(red2 + (ss*2    )*128 + lr);
                float2 va = *(const float2*)(red2 + (ss*2 + 1)*128 + lr);
                z0 += vz.x; z1 += vz.y;
                a0 += va.x; a1 += va.y;
            }
            float zt0 = 1.f / (1.f + __expf(-(wz2.x + z0)));
            float zt1 = 1.f / (1.f + __expf(-(wz2.y + z1)));
            float hc0 = fmaxf(wh2.x + a0, 0.f) * KEEPF;
            float hc1 = fmaxf(wh2.y + a1, 0.f) * KEEPF;
            float hn0 = zt0*hold0 + (1.f - zt0)*hc0;
            float hn1 = zt1*hold1 + (1.f - zt1)*hc1;
            hold0 = hn0; hold1 = hn1;
            float2 o; o.x = hn0; o.y = hn1;
            *(float2*)(Hout + ob) = o;
            __nv_bfloat162 hi2, lo2;
            hi2.x = __float2bfloat16(hn0);
            hi2.y = __float2bfloat16(hn1);
            lo2.x = __float2bfloat16(hn0 - __bfloat162float(hi2.x));
            lo2.y = __float2bfloat16(hn1 - __bfloat162float(hi2.y));
            *(__nv_bfloat162*)(hTh + b_o*HH + jg) = hi2;
            *(__nv_bfloat162*)(hTl + b_o*HH + jg) = lo2;
            // all 64 gate threads done -> single release increment
            asm volatile("bar.sync 1, 64;" ::: "memory");
            if (tid == 0) {
                asm volatile("red.release.gpu.global.add.s32 [%0], 1;"
                             :: "l"(ctr) : "memory");
            }
        } else if (tid == 128 && t < TT-1) {
            int target = (t + 1) * GRID_SCAN;
            int v;
            do {
                asm volatile("ld.acquire.gpu.global.s32 %0, [%1];"
                             : "=r"(v) : "l"(ctr) : "memory");
            } while (v < target);
        }
        __syncthreads();
        if (t == TT-1) break;

        // ---- issue pipelined h reload: 2 k-chunks x (hi + lo) ----
        #pragma unroll
        for (int i = 0; i < 4; i++) {
            int idx = tid + (i << 8);              // 0..1023
            int b = idx >> 6, kq = idx & 63;       // 16B granule (8 bf16)
            uint32_t dofs = (uint32_t)(b*2064 + kq*16);
            const __nv_bfloat16* s0p = hTh + b*HH + kq*8;
            const __nv_bfloat16* s1p = hTl + b*HH + kq*8;
            asm volatile("cp.async.cg.shared.global [%0], [%1], 16;"
                         :: "r"(hi_s + dofs), "l"(s0p) : "memory");
            asm volatile("cp.async.cg.shared.global [%0], [%1], 16;"
                         :: "r"(lo_s + dofs), "l"(s1p) : "memory");
        }
        CPA_COMMIT();
        #pragma unroll
        for (int i = 0; i < 4; i++) {
            int idx = tid + (i << 8);
            int b = idx >> 6, kq = (idx & 63) + 64;
            uint32_t dofs = (uint32_t)(b*2064 + kq*16);
            const __nv_bfloat16* s0p = hTh + b*HH + kq*8;
            const __nv_bfloat16* s1p = hTl + b*HH + kq*8;
            asm volatile("cp.async.cg.shared.global [%0], [%1], 16;"
                         :: "r"(hi_s + dofs), "l"(s0p) : "memory");
            asm volatile("cp.async.cg.shared.global [%0], [%1], 16;"
                         :: "r"(lo_s + dofs), "l"(s1p) : "memory");
        }
        CPA_COMMIT();
    }
}

// =================================================================
extern "C" void kernel_launch(void* const* d_in, const int* in_sizes, int n_in,
                              void* d_out, int out_size)
{
    const float* x     = (const float*)d_in[0];
    const int*   x_len = (const int*)  d_in[1];
    const float* whW0  = (const float*)d_in[2];
    const float* wzW0  = (const float*)d_in[3];
    const float* uhW0  = (const float*)d_in[4];
    const float* uzW0  = (const float*)d_in[5];
    const float* bnh_g0 = (const float*)d_in[6];
    const float* bnh_b0 = (const float*)d_in[7];
    const float* bnh_m0 = (const float*)d_in[8];
    const float* bnh_v0 = (const float*)d_in[9];
    const float* bnz_g0 = (const float*)d_in[10];
    const float* bnz_b0 = (const float*)d_in[11];
    const float* bnz_m0 = (const float*)d_in[12];
    const float* bnz_v0 = (const float*)d_in[13];
    const float* whW1  = (const float*)d_in[14];
    const float* wzW1  = (const float*)d_in[15];
    const float* uhW1  = (const float*)d_in[16];
    const float* uzW1  = (const float*)d_in[17];
    const float* bnh_g1 = (const float*)d_in[18];
    const float* bnh_b1 = (const float*)d_in[19];
    const float* bnh_m1 = (const float*)d_in[20];
    const float* bnh_v1 = (const float*)d_in[21];
    const float* bnz_g1 = (const float*)d_in[22];
    const float* bnz_b1 = (const float*)d_in[23];
    const float* bnz_m1 = (const float*)d_in[24];
    const float* bnz_v1 = (const float*)d_in[25];

    float* out = (float*)d_out;

    float *p_wh, *p_wz, *p_h0; int* p_fl;
    __nv_bfloat16 *p_ahi, *p_alo, *p_whi, *p_wlo, *p_hTh, *p_hTl;
    cudaGetSymbolAddress((void**)&p_wh, g_wh);
    cudaGetSymbolAddress((void**)&p_wz, g_wz);
    cudaGetSymbolAddress((void**)&p_h0, g_h0);
    cudaGetSymbolAddress((void**)&p_fl, g_flags);
    cudaGetSymbolAddress((void**)&p_ahi, g_ahi);
    cudaGetSymbolAddress((void**)&p_alo, g_alo);
    cudaGetSymbolAddress((void**)&p_whi, g_whi);
    cudaGetSymbolAddress((void**)&p_wlo, g_wlo);
    cudaGetSymbolAddress((void**)&p_hTh, g_hTh);
    cudaGetSymbolAddress((void**)&p_hTl, g_hTl);

    int smem_scan = 2*16*HSTR*2 + 8*2*128*4;   // 66048 + 8192 = 74240 B
    cudaFuncSetAttribute(scan_kernel,
        cudaFuncAttributeMaxDynamicSharedMemorySize, smem_scan);

    int smem_gemm = 65536 + 1024;              // 2x(As+Bs) + sc/sh
    cudaFuncSetAttribute(tc_gemm_kernel,
        cudaFuncAttributeMaxDynamicSharedMemorySize, smem_gemm);

    init_kernel<<<32, 256>>>(x_len, out, out_size);

    dim3 gg(HH/128, MTILES);     // (8, 188)

    // ---- layer 0 (K = 512) ----
    split_kernel<<<592, 256>>>(x, p_ahi, p_alo, MTOT*DD);
    split_kernel<<<592, 256>>>(whW0, p_whi, p_wlo, HH*DD);
    tc_gemm_kernel<<<gg, 256, smem_gemm>>>(p_ahi, p_alo, p_whi, p_wlo, p_wh,
                                bnh_g0, bnh_b0, bnh_m0, bnh_v0, DD, MTOT);
    split_kernel<<<592, 256>>>(wzW0, p_whi, p_wlo, HH*DD);
    tc_gemm_kernel<<<gg, 256, smem_gemm>>>(p_ahi, p_alo, p_whi, p_wlo, p_wz,
                                bnz_g0, bnz_b0, bnz_m0, bnz_v0, DD, MTOT);
    scan_kernel<<<GRID_SCAN, 256, smem_scan>>>(p_wh, p_wz, uhW0, uzW0, p_h0,
                                               p_hTh, p_hTl, p_fl);

    // ---- layer 1 (K = 1024) ----
    split_kernel<<<592, 256>>>(p_h0, p_ahi, p_alo, MTOT*HH);
    split_kernel<<<592, 256>>>(whW1, p_whi, p_wlo, HH*HH);
    tc_gemm_kernel<<<gg, 256, smem_gemm>>>(p_ahi, p_alo, p_whi, p_wlo, p_wh,
                                bnh_g1, bnh_b1, bnh_m1, bnh_v1, HH, MTOT);
    split_kernel<<<592, 256>>>(wzW1, p_whi, p_wlo, HH*HH);
    tc_gemm_kernel<<<gg, 256, smem_gemm>>>(p_ahi, p_alo, p_whi, p_wlo, p_wz,
                                bnz_g1, bnz_b1, bnz_m1, bnz_v1, HH, MTOT);
    scan_kernel<<<GRID_SCAN, 256, smem_scan>>>(p_wh, p_wz, uhW1, uzW1, out,
                                               p_hTh, p_hTl, p_fl + FPAD);
}